// round 13
// baseline (speedup 1.0000x reference)
#include <cuda_runtime.h>
#include <cuda_bf16.h>
#include <math.h>

#define NMAX 100000
#define EMAX 1250000
#define HDIM 64
#define SCAN_READY (1 << 30)

typedef unsigned long long ull;

// ---------------- scratch (static device globals; no allocs) ----------------
__device__ __align__(16) float g_t[NMAX * HDIM];
__device__ __align__(16) float g_h[NMAX * HDIM];
__device__ __align__(16) int   g_deg[NMAX];
__device__ float g_dinv[NMAX];
__device__ int   g_rowptr[NMAX + 1];
__device__ int   g_fill[NMAX];
__device__ int   g_csrc[EMAX];
__device__ float g_as[NMAX];
__device__ float g_ad[NMAX];
__device__ float g_p[EMAX];          // fallback path only (deg > 128)
__device__ __align__(16) float g_wc[64 * 64];
__device__ int   g_bsum[128];

__device__ __forceinline__ float leaky(float v) { return v > 0.f ? v : 0.2f * v; }

__device__ __forceinline__ void ffma2(ull& acc, ull a, ull b) {
    asm("fma.rn.f32x2 %0, %1, %2, %0;" : "+l"(acc) : "l"(a), "l"(b));
}
__device__ __forceinline__ void fadd2(ull& acc, ull v) {
    asm("add.rn.f32x2 %0, %0, %1;" : "+l"(acc) : "l"(v));
}
__device__ __forceinline__ ull pack2(float lo, float hi) {
    ull r;
    asm("mov.b64 %0, {%1, %2};" : "=l"(r) : "f"(lo), "f"(hi));
    return r;
}
__device__ __forceinline__ float2 unpack2(ull v) {
    float2 r;
    asm("mov.b64 {%0, %1}, %2;" : "=f"(r.x), "=f"(r.y) : "l"(v));
    return r;
}

// ---------------- count + init (geO zero, bsum flags zero, packed Wc) -------
__global__ void k_count_init(const int* __restrict__ dst, int e, int ebN,
                             float* __restrict__ geO,
                             const float* __restrict__ Wopt,
                             const float* __restrict__ Wb1) {
    int b = blockIdx.x;
    if (b < ebN) {
        int i = b * 256 + threadIdx.x;
        if (i < e) atomicAdd(&g_deg[dst[i]], 1);
        return;
    }
    int i = (b - ebN) * 256 + threadIdx.x;
    if (i < 64) geO[i] = 0.f;
    if (i < 128) g_bsum[i] = 0;
    if (i < 4096) {
        int k = i >> 6, c = i & 63;
        float v = 0.f;
        if (c < 10) v = Wopt[k * 10 + c];
        else if (c < 42) v = Wb1[k * 32 + (c - 10)];
        g_wc[i] = v;
    }
}

// ------------- single-pass exclusive scan with parallel lookback ------------
__global__ void k_scan_one(int n, int e) {
    __shared__ int sm[256];
    __shared__ int sl[256];
    int b = blockIdx.x, t = threadIdx.x;
    int base = b * 1024 + t * 4;
    int d[4];
    int s = 0;
#pragma unroll
    for (int j = 0; j < 4; j++) {
        int i = base + j;
        d[j] = (i < n) ? g_deg[i] : 0;
        s += d[j];
    }
    sm[t] = s;
    __syncthreads();
#pragma unroll
    for (int off = 1; off < 256; off <<= 1) {
        int v = (t >= off) ? sm[t - off] : 0;
        __syncthreads();
        sm[t] += v;
        __syncthreads();
    }
    if (t == 0) atomicExch(&g_bsum[b], sm[255] | SCAN_READY);

    int part = 0;
    if (t < b) {
        volatile int* vb = g_bsum;
        int v;
        do { v = vb[t]; } while (!(v & SCAN_READY));
        part = v & (SCAN_READY - 1);
    }
    sl[t] = part;
    __syncthreads();
#pragma unroll
    for (int off = 128; off; off >>= 1) {
        if (t < off) sl[t] += sl[t + off];
        __syncthreads();
    }
    int run = sl[0] + sm[t] - s;
#pragma unroll
    for (int j = 0; j < 4; j++) {
        int i = base + j;
        if (i < n) {
            g_rowptr[i] = run;
            g_fill[i] = run;
            g_dinv[i] = rsqrtf((float)(d[j] + 1));  // +1 self-loop
            run += d[j];
        }
    }
    if (b == 0 && t == 0) g_rowptr[n] = e;
}

// ---------------- GEMM body: C[n,64] = A[n,K] @ B[K,64], 128-row tile -------
// EPI: 0 plain | 1 scale row by g_dinv[row] | 2 also emit g_as/g_ad
template <int K, int EPI>
__device__ __forceinline__ void gemm_body(const float* __restrict__ A,
                                          const float* __restrict__ B,
                                          float* __restrict__ C, int n, int bid,
                                          const float* __restrict__ av1,
                                          const float* __restrict__ av2) {
    constexpr int KT = (K > 32) ? 32 : K;
    __shared__ __align__(16) float As[KT][132];
    __shared__ __align__(16) float Bs[K][64];
    int t = threadIdx.x;
    int r0b = bid * 128;
    int tx = t & 15, ty = t >> 4;

#pragma unroll
    for (int j = 0; j < (K * 64) / 256; j++) {
        int idx = t + j * 256;
        Bs[idx >> 6][idx & 63] = B[idx];
    }

    ull acc[4][4] = {};

    for (int kt = 0; kt < K; kt += KT) {
        __syncthreads();
#pragma unroll
        for (int j = 0; j < (KT * 128) / 256; j++) {
            int idx = t + j * 256;
            int r = idx / KT, k = idx % KT;
            int gr = r0b + r;
            As[k][r] = (gr < n) ? A[gr * K + kt + k] : 0.f;
        }
        __syncthreads();
#pragma unroll
        for (int kk = 0; kk < KT; kk++) {
            float4 bq = *(const float4*)&Bs[kt + kk][tx * 4];
            ull b0 = pack2(bq.x, bq.x), b1 = pack2(bq.y, bq.y);
            ull b2 = pack2(bq.z, bq.z), b3 = pack2(bq.w, bq.w);
            ulonglong2 aA = *(const ulonglong2*)&As[kk][ty * 8];
            ulonglong2 aB = *(const ulonglong2*)&As[kk][ty * 8 + 4];
            ffma2(acc[0][0], aA.x, b0); ffma2(acc[0][1], aA.x, b1);
            ffma2(acc[0][2], aA.x, b2); ffma2(acc[0][3], aA.x, b3);
            ffma2(acc[1][0], aA.y, b0); ffma2(acc[1][1], aA.y, b1);
            ffma2(acc[1][2], aA.y, b2); ffma2(acc[1][3], aA.y, b3);
            ffma2(acc[2][0], aB.x, b0); ffma2(acc[2][1], aB.x, b1);
            ffma2(acc[2][2], aB.x, b2); ffma2(acc[2][3], aB.x, b3);
            ffma2(acc[3][0], aB.y, b0); ffma2(acc[3][1], aB.y, b1);
            ffma2(acc[3][2], aB.y, b2); ffma2(acc[3][3], aB.y, b3);
        }
    }

    float4 as4, ad4;
    if (EPI == 2) {
        as4 = *(const float4*)&av1[tx * 4];
        ad4 = *(const float4*)&av2[tx * 4];
    }
#pragma unroll
    for (int rp = 0; rp < 4; rp++) {
        float2 c0 = unpack2(acc[rp][0]), c1 = unpack2(acc[rp][1]);
        float2 c2 = unpack2(acc[rp][2]), c3 = unpack2(acc[rp][3]);
        float4 v[2] = { make_float4(c0.x, c1.x, c2.x, c3.x),
                        make_float4(c0.y, c1.y, c2.y, c3.y) };
#pragma unroll
        for (int h = 0; h < 2; h++) {
            int gr = r0b + ty * 8 + rp * 2 + h;
            float4 cv = v[h];
            if (EPI == 1 && gr < n) {
                float s = g_dinv[gr];
                cv.x *= s; cv.y *= s; cv.z *= s; cv.w *= s;
            }
            if (gr < n) *(float4*)&C[gr * 64 + tx * 4] = cv;
            if (EPI == 2) {
                float ps = cv.x * as4.x + cv.y * as4.y + cv.z * as4.z + cv.w * as4.w;
                float pd = cv.x * ad4.x + cv.y * ad4.y + cv.z * ad4.z + cv.w * ad4.w;
#pragma unroll
                for (int o = 8; o; o >>= 1) {
                    ps += __shfl_xor_sync(0xFFFFFFFFu, ps, o);
                    pd += __shfl_xor_sync(0xFFFFFFFFu, pd, o);
                }
                if (tx == 0 && gr < n) { g_as[gr] = ps; g_ad[gr] = pd; }
            }
        }
    }
}

template <int K, int EPI>
__global__ __launch_bounds__(256) void k_gemm128(const float* __restrict__ A,
                                                 const float* __restrict__ B,
                                                 float* __restrict__ C, int n,
                                                 const float* __restrict__ av1,
                                                 const float* __restrict__ av2) {
    gemm_body<K, EPI>(A, B, C, n, blockIdx.x, av1, av2);
}

// ---------------- fused: CSR fill blocks + layer-1 GEMM blocks ---------------
__global__ __launch_bounds__(256) void k_fill_gemm(const int* __restrict__ src,
                                                   const int* __restrict__ dst,
                                                   int e, int ebN,
                                                   const float* __restrict__ A,
                                                   const float* __restrict__ B,
                                                   float* __restrict__ C, int n) {
    if ((int)blockIdx.x < ebN) {
        int i = blockIdx.x * 256 + threadIdx.x;
        if (i < e) {
            int d = dst[i];
            int p = atomicAdd(&g_fill[d], 1);
            g_csrc[p] = src[i];
        }
        return;
    }
    gemm_body<32, 1>(A, B, C, n, blockIdx.x - ebN, nullptr, nullptr);
}

// ---------------- head GEMM + fused epilogue (no tc materialization) --------
__global__ __launch_bounds__(256) void k_gemm_head(const float* __restrict__ A,
                                                   const float* __restrict__ B,
                                                   int n,
                                                   const float* __restrict__ bopt,
                                                   const float* __restrict__ bb1,
                                                   const float* __restrict__ Wb2,
                                                   const float* __restrict__ bb2,
                                                   float* __restrict__ optO,
                                                   float* __restrict__ botO,
                                                   float* __restrict__ geO,
                                                   float invn) {
    constexpr int K = 64, KT = 32;
    __shared__ __align__(16) float As[KT][132];
    __shared__ __align__(16) float Bs[K][64];
    __shared__ float sge[64];
    int t = threadIdx.x;
    int r0b = blockIdx.x * 128;
    int tx = t & 15, ty = t >> 4;

    if (t < 64) sge[t] = 0.f;
#pragma unroll
    for (int j = 0; j < (K * 64) / 256; j++) {
        int idx = t + j * 256;
        Bs[idx >> 6][idx & 63] = B[idx];
    }

    ull acc[4][4] = {};

    for (int kt = 0; kt < K; kt += KT) {
        __syncthreads();
#pragma unroll
        for (int j = 0; j < (KT * 128) / 256; j++) {
            int idx = t + j * 256;
            int r = idx / KT, k = idx % KT;
            int gr = r0b + r;
            As[k][r] = (gr < n) ? A[gr * K + kt + k] : 0.f;
        }
        __syncthreads();
        {
            int kk = t & 31, r0 = (t >> 5) * 16;
            float gp = 0.f;
#pragma unroll
            for (int r = 0; r < 16; r++) gp += As[kk][r0 + r];
            atomicAdd(&sge[kt + kk], gp);
        }
#pragma unroll
        for (int kk = 0; kk < KT; kk++) {
            float4 bq = *(const float4*)&Bs[kt + kk][tx * 4];
            ull b0 = pack2(bq.x, bq.x), b1 = pack2(bq.y, bq.y);
            ull b2 = pack2(bq.z, bq.z), b3 = pack2(bq.w, bq.w);
            ulonglong2 aA = *(const ulonglong2*)&As[kk][ty * 8];
            ulonglong2 aB = *(const ulonglong2*)&As[kk][ty * 8 + 4];
            ffma2(acc[0][0], aA.x, b0); ffma2(acc[0][1], aA.x, b1);
            ffma2(acc[0][2], aA.x, b2); ffma2(acc[0][3], aA.x, b3);
            ffma2(acc[1][0], aA.y, b0); ffma2(acc[1][1], aA.y, b1);
            ffma2(acc[1][2], aA.y, b2); ffma2(acc[1][3], aA.y, b3);
            ffma2(acc[2][0], aB.x, b0); ffma2(acc[2][1], aB.x, b1);
            ffma2(acc[2][2], aB.x, b2); ffma2(acc[2][3], aB.x, b3);
            ffma2(acc[3][0], aB.y, b0); ffma2(acc[3][1], aB.y, b1);
            ffma2(acc[3][2], aB.y, b2); ffma2(acc[3][3], aB.y, b3);
        }
    }

    float bb2v = bb2[0];
    float boptv[4], bb1v[4], wb2v[4];
#pragma unroll
    for (int c4 = 0; c4 < 4; c4++) {
        int c = tx * 4 + c4;
        boptv[c4] = (c < 10) ? bopt[c] : 0.f;
        bb1v[c4]  = (c >= 10 && c < 42) ? bb1[c - 10] : 0.f;
        wb2v[c4]  = (c >= 10 && c < 42) ? Wb2[c - 10] : 0.f;
    }

#pragma unroll
    for (int rp = 0; rp < 4; rp++) {
        float2 c0 = unpack2(acc[rp][0]), c1 = unpack2(acc[rp][1]);
        float2 c2 = unpack2(acc[rp][2]), c3 = unpack2(acc[rp][3]);
        float vv[2][4] = { {c0.x, c1.x, c2.x, c3.x}, {c0.y, c1.y, c2.y, c3.y} };
#pragma unroll
        for (int h = 0; h < 2; h++) {
            int gr = r0b + ty * 8 + rp * 2 + h;
            float part = 0.f;
#pragma unroll
            for (int c4 = 0; c4 < 4; c4++)
                part += fmaxf(vv[h][c4] + bb1v[c4], 0.f) * wb2v[c4];
#pragma unroll
            for (int o = 8; o; o >>= 1)
                part += __shfl_xor_sync(0xFFFFFFFFu, part, o);
            if (gr < n) {
#pragma unroll
                for (int c4 = 0; c4 < 4; c4++) {
                    int c = tx * 4 + c4;
                    if (c < 10) optO[gr * 10 + c] = vv[h][c4] + boptv[c4];
                }
                if (tx == 0)
                    botO[gr] = 1.f / (1.f + __expf(-(part + bb2v)));
            }
        }
    }

    __syncthreads();
    if (t < 64) atomicAdd(&geO[t], sge[t] * invn);
}

// ---------------- GCN aggregation: coalesced index fetch + shfl broadcast ---
// Edge indices loaded coalesced (32/wavefront) instead of 1 broadcast LDG per
// edge; distribution via shfl (MIO pipe) keeps index traffic off L1tex.
__global__ void k_gcn_agg(const float* __restrict__ t, const float* __restrict__ bias,
                          float* __restrict__ out, int n) {
    int w = (blockIdx.x * blockDim.x + threadIdx.x) >> 5;
    int lane = threadIdx.x & 31;
    if (w >= n) return;
    const ull* __restrict__ T = (const ull*)t;
    int s0 = g_rowptr[w], s1 = g_rowptr[w + 1];
    int deg = s1 - s0;
    ull acc0 = T[w * 32 + lane];             // self-loop (pre-scaled)
    ull acc1 = 0;                            // second chain breaks FADD2 RAW

    if (deg <= 128) {
        int cs[4];
#pragma unroll
        for (int j = 0; j < 4; j++) {
            int e = s0 + j * 32 + lane;      // coalesced: 32 indices / wavefront
            cs[j] = (e < s1) ? g_csrc[e] : 0;
        }
#pragma unroll
        for (int j = 0; j < 4; j++) {
            int base = s0 + j * 32;
            if (base >= s1) break;
            int cnt = min(32, s1 - base);
            int l = 0;
            for (; l + 3 < cnt; l += 4) {
                int i0 = __shfl_sync(0xFFFFFFFFu, cs[j], l);
                int i1 = __shfl_sync(0xFFFFFFFFu, cs[j], l + 1);
                int i2 = __shfl_sync(0xFFFFFFFFu, cs[j], l + 2);
                int i3 = __shfl_sync(0xFFFFFFFFu, cs[j], l + 3);
                ull v0 = T[i0 * 32 + lane], v1 = T[i1 * 32 + lane];
                ull v2 = T[i2 * 32 + lane], v3 = T[i3 * 32 + lane];
                fadd2(acc0, v0); fadd2(acc1, v1);
                fadd2(acc0, v2); fadd2(acc1, v3);
            }
            for (; l < cnt; l++) {
                int i0 = __shfl_sync(0xFFFFFFFFu, cs[j], l);
                fadd2(acc0, T[i0 * 32 + lane]);
            }
        }
    } else {
        for (int e = s0; e < s1; e++) fadd2(acc0, T[g_csrc[e] * 32 + lane]);
    }
    fadd2(acc0, acc1);
    float2 a = unpack2(acc0);
    float di = g_dinv[w];
    float2 bp = *(const float2*)&bias[lane * 2];
    float2 o = make_float2(fmaxf(a.x * di + bp.x, 0.f), fmaxf(a.y * di + bp.y, 0.f));
    *(float2*)&out[w * 64 + lane * 2] = o;
}

// ---------------- GAT aggregation (re-zeroes g_deg for next replay) ---------
__global__ void k_gat(const float* __restrict__ t, const float* __restrict__ bias,
                      float* __restrict__ out, int n) {
    int gid = blockIdx.x * blockDim.x + threadIdx.x;
    if (gid < n) g_deg[gid] = 0;   // consumed by scan; reset for next replay
    int w = gid >> 5;
    int lane = threadIdx.x & 31;
    if (w >= n) return;
    const ull* __restrict__ T = (const ull*)t;
    int s0 = g_rowptr[w], s1 = g_rowptr[w + 1];
    int deg = s1 - s0;
    float adi = g_ad[w];
    float eself = leaky(g_as[w] + adi);
    ull acc0 = 0, acc1 = 0;

    if (deg <= 128) {
        int cs[4];
        float pv[4];
        float m = eself;
#pragma unroll
        for (int j = 0; j < 4; j++) {
            int e = s0 + j * 32 + lane;
            if (e < s1) {
                int s = g_csrc[e];
                cs[j] = s;
                float v = leaky(g_as[s] + adi);
                pv[j] = v;
                m = fmaxf(m, v);
            } else { cs[j] = 0; pv[j] = -1e30f; }
        }
#pragma unroll
        for (int o = 16; o; o >>= 1) m = fmaxf(m, __shfl_xor_sync(0xFFFFFFFFu, m, o));

        float sum = 0.f;
#pragma unroll
        for (int j = 0; j < 4; j++) {
            pv[j] = __expf(pv[j] - m);   // inactive lanes underflow to 0
            sum += pv[j];
        }
#pragma unroll
        for (int o = 16; o; o >>= 1) sum += __shfl_xor_sync(0xFFFFFFFFu, sum, o);
        float es = __expf(eself - m);
        float inv = 1.f / (sum + es);

        float ps = es * inv;
        ffma2(acc0, T[w * 32 + lane], pack2(ps, ps));

#pragma unroll
        for (int j = 0; j < 4; j++) {
            int base = s0 + j * 32;
            if (base >= s1) break;
            int cnt = min(32, s1 - base);
            int l = 0;
            for (; l + 1 < cnt; l += 2) {
                int   sA = __shfl_sync(0xFFFFFFFFu, cs[j], l);
                int   sB = __shfl_sync(0xFFFFFFFFu, cs[j], l + 1);
                float pA = __shfl_sync(0xFFFFFFFFu, pv[j], l) * inv;
                float pB = __shfl_sync(0xFFFFFFFFu, pv[j], l + 1) * inv;
                ull vA = T[sA * 32 + lane], vB = T[sB * 32 + lane];
                ffma2(acc0, vA, pack2(pA, pA));
                ffma2(acc1, vB, pack2(pB, pB));
            }
            if (l < cnt) {
                int   sA = __shfl_sync(0xFFFFFFFFu, cs[j], l);
                float pA = __shfl_sync(0xFFFFFFFFu, pv[j], l) * inv;
                ffma2(acc0, T[sA * 32 + lane], pack2(pA, pA));
            }
        }
    } else {
        float m = eself;
        for (int e = s0 + lane; e < s1; e += 32) {
            float v = leaky(g_as[g_csrc[e]] + adi);
            g_p[e] = v;
            m = fmaxf(m, v);
        }
#pragma unroll
        for (int o = 16; o; o >>= 1) m = fmaxf(m, __shfl_xor_sync(0xFFFFFFFFu, m, o));
        float sum = 0.f;
        for (int e = s0 + lane; e < s1; e += 32) {
            float pe = __expf(g_p[e] - m);
            g_p[e] = pe;
            sum += pe;
        }
#pragma unroll
        for (int o = 16; o; o >>= 1) sum += __shfl_xor_sync(0xFFFFFFFFu, sum, o);
        float es = __expf(eself - m);
        float inv = 1.f / (sum + es);
        float ps = es * inv;
        ffma2(acc0, T[w * 32 + lane], pack2(ps, ps));
        for (int e = s0; e < s1; e++) {
            int sA = g_csrc[e];
            float aA = g_p[e] * inv;
            ffma2(acc0, T[sA * 32 + lane], pack2(aA, aA));
        }
    }
    fadd2(acc0, acc1);
    float2 a = unpack2(acc0);
    float2 bp = *(const float2*)&bias[lane * 2];
    float2 o = make_float2(fmaxf(a.x + bp.x, 0.f), fmaxf(a.y + bp.y, 0.f));
    *(float2*)&out[w * 64 + lane * 2] = o;
}

// ---------------- launcher ----------------
extern "C" void kernel_launch(void* const* d_in, const int* in_sizes, int n_in,
                              void* d_out, int out_size) {
    const float* x     = (const float*)d_in[0];
    const int*   ei    = (const int*)d_in[1];
    const float* W1    = (const float*)d_in[2];
    const float* b1    = (const float*)d_in[3];
    const float* W2    = (const float*)d_in[4];
    const float* a_src = (const float*)d_in[5];
    const float* a_dst = (const float*)d_in[6];
    const float* b2    = (const float*)d_in[7];
    const float* W3    = (const float*)d_in[8];
    const float* b3    = (const float*)d_in[9];
    const float* Wopt  = (const float*)d_in[10];
    const float* bopt  = (const float*)d_in[11];
    const float* Wb1   = (const float*)d_in[12];
    const float* bb1   = (const float*)d_in[13];
    const float* Wb2   = (const float*)d_in[14];
    const float* bb2   = (const float*)d_in[15];

    int n = in_sizes[0] / 32;
    int e = in_sizes[1] / 2;
    const int* src = ei;
    const int* dst = ei + e;

    float* out  = (float*)d_out;
    float* optO = out;
    float* botO = out + (size_t)n * 10;
    float* geO  = botO + n;

    float *p_t, *p_h, *p_wc;
    cudaGetSymbolAddress((void**)&p_t, g_t);
    cudaGetSymbolAddress((void**)&p_h, g_h);
    cudaGetSymbolAddress((void**)&p_wc, g_wc);

    int eb256  = (e + 255) / 256;
    int warpsB = (n + 7) / 8;
    int gemmB  = (n + 127) / 128;
    int scanB  = (n + 1023) / 1024;

    // structure: count (+ init extras) -> one-kernel scan -> fill (+gemm1)
    k_count_init<<<eb256 + 17, 256>>>(dst, e, eb256, geO, Wopt, Wb1);
    k_scan_one<<<scanB, 256>>>(n, e);
    k_fill_gemm<<<eb256 + gemmB, 256>>>(src, dst, e, eb256, x, W1, p_t, n);

    // layer 1: GCN aggregation + relu
    k_gcn_agg<<<warpsB, 256>>>(p_t, b1, p_h, n);

    // layer 2: GAT(64->64) + relu (GEMM epilogue emits alpha_src/alpha_dst)
    k_gemm128<64, 2><<<gemmB, 256>>>(p_h, W2, p_t, n, a_src, a_dst);
    k_gat<<<warpsB, 256>>>(p_t, b2, p_h, n);

    // layer 3: GCN(64->64) + relu
    k_gemm128<64, 1><<<gemmB, 256>>>(p_h, W3, p_t, n, nullptr, nullptr);
    k_gcn_agg<<<warpsB, 256>>>(p_t, b3, p_h, n);

    // heads: GEMM with packed [Wopt|Wb1] + fully fused epilogue
    k_gemm_head<<<gemmB, 256>>>(p_h, p_wc, n, bopt, bb1, Wb2, bb2,
                                optO, botO, geO, 1.0f / (float)n);
}

// round 14
// speedup vs baseline: 1.1349x; 1.1349x over previous
#include <cuda_runtime.h>
#include <cuda_fp16.h>
#include <math.h>

#define NMAX 100000
#define EMAX 1250000
#define HDIM 64
#define SCAN_READY (1 << 30)

typedef unsigned long long ull;
typedef unsigned int uint;

// ---------------- scratch (static device globals; no allocs) ----------------
__device__ __align__(16) __half g_t[NMAX * HDIM];   // fp16 gathered intermediate
__device__ __align__(16) float g_h[NMAX * HDIM];
__device__ __align__(16) int   g_deg[NMAX];
__device__ float g_dinv[NMAX];
__device__ int   g_rowptr[NMAX + 1];
__device__ int   g_fill[NMAX];
__device__ int   g_csrc[EMAX];
__device__ float g_as[NMAX];
__device__ float g_ad[NMAX];
__device__ float g_p[EMAX];          // fallback path only (deg > 128)
__device__ __align__(16) float g_wc[64 * 64];
__device__ int   g_bsum[128];

__device__ __forceinline__ float leaky(float v) { return v > 0.f ? v : 0.2f * v; }

__device__ __forceinline__ void ffma2(ull& acc, ull a, ull b) {
    asm("fma.rn.f32x2 %0, %1, %2, %0;" : "+l"(acc) : "l"(a), "l"(b));
}
__device__ __forceinline__ ull pack2(float lo, float hi) {
    ull r;
    asm("mov.b64 %0, {%1, %2};" : "=l"(r) : "f"(lo), "f"(hi));
    return r;
}
__device__ __forceinline__ float2 unpack2(ull v) {
    float2 r;
    asm("mov.b64 {%0, %1}, %2;" : "=f"(r.x), "=f"(r.y) : "l"(v));
    return r;
}
// half2 (as uint) -> float2
__device__ __forceinline__ float2 h2f(uint v) {
    __half2 h = *reinterpret_cast<__half2*>(&v);
    return __half22float2(h);
}
__device__ __forceinline__ uint f2h(float a, float b) {
    __half2 h = __float22half2_rn(make_float2(a, b));
    return *reinterpret_cast<uint*>(&h);
}

// ---------------- count + init (geO zero, bsum flags zero, packed Wc) -------
__global__ void k_count_init(const int* __restrict__ dst, int e, int ebN,
                             float* __restrict__ geO,
                             const float* __restrict__ Wopt,
                             const float* __restrict__ Wb1) {
    int b = blockIdx.x;
    if (b < ebN) {
        int i = b * 256 + threadIdx.x;
        if (i < e) atomicAdd(&g_deg[dst[i]], 1);
        return;
    }
    int i = (b - ebN) * 256 + threadIdx.x;
    if (i < 64) geO[i] = 0.f;
    if (i < 128) g_bsum[i] = 0;
    if (i < 4096) {
        int k = i >> 6, c = i & 63;
        float v = 0.f;
        if (c < 10) v = Wopt[k * 10 + c];
        else if (c < 42) v = Wb1[k * 32 + (c - 10)];
        g_wc[i] = v;
    }
}

// ------------- single-pass exclusive scan with parallel lookback ------------
__global__ void k_scan_one(int n, int e) {
    __shared__ int sm[256];
    __shared__ int sl[256];
    int b = blockIdx.x, t = threadIdx.x;
    int base = b * 1024 + t * 4;
    int d[4];
    int s = 0;
#pragma unroll
    for (int j = 0; j < 4; j++) {
        int i = base + j;
        d[j] = (i < n) ? g_deg[i] : 0;
        s += d[j];
    }
    sm[t] = s;
    __syncthreads();
#pragma unroll
    for (int off = 1; off < 256; off <<= 1) {
        int v = (t >= off) ? sm[t - off] : 0;
        __syncthreads();
        sm[t] += v;
        __syncthreads();
    }
    if (t == 0) atomicExch(&g_bsum[b], sm[255] | SCAN_READY);

    int part = 0;
    if (t < b) {
        volatile int* vb = g_bsum;
        int v;
        do { v = vb[t]; } while (!(v & SCAN_READY));
        part = v & (SCAN_READY - 1);
    }
    sl[t] = part;
    __syncthreads();
#pragma unroll
    for (int off = 128; off; off >>= 1) {
        if (t < off) sl[t] += sl[t + off];
        __syncthreads();
    }
    int run = sl[0] + sm[t] - s;
#pragma unroll
    for (int j = 0; j < 4; j++) {
        int i = base + j;
        if (i < n) {
            g_rowptr[i] = run;
            g_fill[i] = run;
            g_dinv[i] = rsqrtf((float)(d[j] + 1));  // +1 self-loop
            run += d[j];
        }
    }
    if (b == 0 && t == 0) g_rowptr[n] = e;
}

// ---------------- GEMM body: C[n,64](fp16) = A[n,K](fp32) @ B[K,64] ---------
// EPI: 0 plain | 1 scale row by g_dinv[row] | 2 also emit g_as/g_ad
template <int K, int EPI>
__device__ __forceinline__ void gemm_body(const float* __restrict__ A,
                                          const float* __restrict__ B,
                                          __half* __restrict__ C, int n, int bid,
                                          const float* __restrict__ av1,
                                          const float* __restrict__ av2) {
    constexpr int KT = (K > 32) ? 32 : K;
    __shared__ __align__(16) float As[KT][132];
    __shared__ __align__(16) float Bs[K][64];
    int t = threadIdx.x;
    int r0b = bid * 128;
    int tx = t & 15, ty = t >> 4;

#pragma unroll
    for (int j = 0; j < (K * 64) / 256; j++) {
        int idx = t + j * 256;
        Bs[idx >> 6][idx & 63] = B[idx];
    }

    ull acc[4][4] = {};

    for (int kt = 0; kt < K; kt += KT) {
        __syncthreads();
#pragma unroll
        for (int j = 0; j < (KT * 128) / 256; j++) {
            int idx = t + j * 256;
            int r = idx / KT, k = idx % KT;
            int gr = r0b + r;
            As[k][r] = (gr < n) ? A[gr * K + kt + k] : 0.f;
        }
        __syncthreads();
#pragma unroll
        for (int kk = 0; kk < KT; kk++) {
            float4 bq = *(const float4*)&Bs[kt + kk][tx * 4];
            ull b0 = pack2(bq.x, bq.x), b1 = pack2(bq.y, bq.y);
            ull b2 = pack2(bq.z, bq.z), b3 = pack2(bq.w, bq.w);
            ulonglong2 aA = *(const ulonglong2*)&As[kk][ty * 8];
            ulonglong2 aB = *(const ulonglong2*)&As[kk][ty * 8 + 4];
            ffma2(acc[0][0], aA.x, b0); ffma2(acc[0][1], aA.x, b1);
            ffma2(acc[0][2], aA.x, b2); ffma2(acc[0][3], aA.x, b3);
            ffma2(acc[1][0], aA.y, b0); ffma2(acc[1][1], aA.y, b1);
            ffma2(acc[1][2], aA.y, b2); ffma2(acc[1][3], aA.y, b3);
            ffma2(acc[2][0], aB.x, b0); ffma2(acc[2][1], aB.x, b1);
            ffma2(acc[2][2], aB.x, b2); ffma2(acc[2][3], aB.x, b3);
            ffma2(acc[3][0], aB.y, b0); ffma2(acc[3][1], aB.y, b1);
            ffma2(acc[3][2], aB.y, b2); ffma2(acc[3][3], aB.y, b3);
        }
    }

    float4 as4, ad4;
    if (EPI == 2) {
        as4 = *(const float4*)&av1[tx * 4];
        ad4 = *(const float4*)&av2[tx * 4];
    }
#pragma unroll
    for (int rp = 0; rp < 4; rp++) {
        float2 c0 = unpack2(acc[rp][0]), c1 = unpack2(acc[rp][1]);
        float2 c2 = unpack2(acc[rp][2]), c3 = unpack2(acc[rp][3]);
        float4 v[2] = { make_float4(c0.x, c1.x, c2.x, c3.x),
                        make_float4(c0.y, c1.y, c2.y, c3.y) };
#pragma unroll
        for (int h = 0; h < 2; h++) {
            int gr = r0b + ty * 8 + rp * 2 + h;
            float4 cv = v[h];
            if (EPI == 1 && gr < n) {
                float s = g_dinv[gr];
                cv.x *= s; cv.y *= s; cv.z *= s; cv.w *= s;
            }
            if (gr < n) {
                uint2 st = make_uint2(f2h(cv.x, cv.y), f2h(cv.z, cv.w));
                *(uint2*)&C[gr * 64 + tx * 4] = st;   // STG.64, fp16 row
            }
            if (EPI == 2) {
                float ps = cv.x * as4.x + cv.y * as4.y + cv.z * as4.z + cv.w * as4.w;
                float pd = cv.x * ad4.x + cv.y * ad4.y + cv.z * ad4.z + cv.w * ad4.w;
#pragma unroll
                for (int o = 8; o; o >>= 1) {
                    ps += __shfl_xor_sync(0xFFFFFFFFu, ps, o);
                    pd += __shfl_xor_sync(0xFFFFFFFFu, pd, o);
                }
                if (tx == 0 && gr < n) { g_as[gr] = ps; g_ad[gr] = pd; }
            }
        }
    }
}

template <int K, int EPI>
__global__ __launch_bounds__(256) void k_gemm128(const float* __restrict__ A,
                                                 const float* __restrict__ B,
                                                 __half* __restrict__ C, int n,
                                                 const float* __restrict__ av1,
                                                 const float* __restrict__ av2) {
    gemm_body<K, EPI>(A, B, C, n, blockIdx.x, av1, av2);
}

// ---------------- fused: CSR fill blocks + layer-1 GEMM blocks ---------------
__global__ __launch_bounds__(256) void k_fill_gemm(const int* __restrict__ src,
                                                   const int* __restrict__ dst,
                                                   int e, int ebN,
                                                   const float* __restrict__ A,
                                                   const float* __restrict__ B,
                                                   __half* __restrict__ C, int n) {
    if ((int)blockIdx.x < ebN) {
        int i = blockIdx.x * 256 + threadIdx.x;
        if (i < e) {
            int d = dst[i];
            int p = atomicAdd(&g_fill[d], 1);
            g_csrc[p] = src[i];
        }
        return;
    }
    gemm_body<32, 1>(A, B, C, n, blockIdx.x - ebN, nullptr, nullptr);
}

// ---------------- head GEMM + fused epilogue (fp32 A = h3, no tc buffer) ----
__global__ __launch_bounds__(256) void k_gemm_head(const float* __restrict__ A,
                                                   const float* __restrict__ B,
                                                   int n,
                                                   const float* __restrict__ bopt,
                                                   const float* __restrict__ bb1,
                                                   const float* __restrict__ Wb2,
                                                   const float* __restrict__ bb2,
                                                   float* __restrict__ optO,
                                                   float* __restrict__ botO,
                                                   float* __restrict__ geO,
                                                   float invn) {
    constexpr int K = 64, KT = 32;
    __shared__ __align__(16) float As[KT][132];
    __shared__ __align__(16) float Bs[K][64];
    __shared__ float sge[64];
    int t = threadIdx.x;
    int r0b = blockIdx.x * 128;
    int tx = t & 15, ty = t >> 4;

    if (t < 64) sge[t] = 0.f;
#pragma unroll
    for (int j = 0; j < (K * 64) / 256; j++) {
        int idx = t + j * 256;
        Bs[idx >> 6][idx & 63] = B[idx];
    }

    ull acc[4][4] = {};

    for (int kt = 0; kt < K; kt += KT) {
        __syncthreads();
#pragma unroll
        for (int j = 0; j < (KT * 128) / 256; j++) {
            int idx = t + j * 256;
            int r = idx / KT, k = idx % KT;
            int gr = r0b + r;
            As[k][r] = (gr < n) ? A[gr * K + kt + k] : 0.f;
        }
        __syncthreads();
        {
            int kk = t & 31, r0 = (t >> 5) * 16;
            float gp = 0.f;
#pragma unroll
            for (int r = 0; r < 16; r++) gp += As[kk][r0 + r];
            atomicAdd(&sge[kt + kk], gp);
        }
#pragma unroll
        for (int kk = 0; kk < KT; kk++) {
            float4 bq = *(const float4*)&Bs[kt + kk][tx * 4];
            ull b0 = pack2(bq.x, bq.x), b1 = pack2(bq.y, bq.y);
            ull b2 = pack2(bq.z, bq.z), b3 = pack2(bq.w, bq.w);
            ulonglong2 aA = *(const ulonglong2*)&As[kk][ty * 8];
            ulonglong2 aB = *(const ulonglong2*)&As[kk][ty * 8 + 4];
            ffma2(acc[0][0], aA.x, b0); ffma2(acc[0][1], aA.x, b1);
            ffma2(acc[0][2], aA.x, b2); ffma2(acc[0][3], aA.x, b3);
            ffma2(acc[1][0], aA.y, b0); ffma2(acc[1][1], aA.y, b1);
            ffma2(acc[1][2], aA.y, b2); ffma2(acc[1][3], aA.y, b3);
            ffma2(acc[2][0], aB.x, b0); ffma2(acc[2][1], aB.x, b1);
            ffma2(acc[2][2], aB.x, b2); ffma2(acc[2][3], aB.x, b3);
            ffma2(acc[3][0], aB.y, b0); ffma2(acc[3][1], aB.y, b1);
            ffma2(acc[3][2], aB.y, b2); ffma2(acc[3][3], aB.y, b3);
        }
    }

    float bb2v = bb2[0];
    float boptv[4], bb1v[4], wb2v[4];
#pragma unroll
    for (int c4 = 0; c4 < 4; c4++) {
        int c = tx * 4 + c4;
        boptv[c4] = (c < 10) ? bopt[c] : 0.f;
        bb1v[c4]  = (c >= 10 && c < 42) ? bb1[c - 10] : 0.f;
        wb2v[c4]  = (c >= 10 && c < 42) ? Wb2[c - 10] : 0.f;
    }

#pragma unroll
    for (int rp = 0; rp < 4; rp++) {
        float2 c0 = unpack2(acc[rp][0]), c1 = unpack2(acc[rp][1]);
        float2 c2 = unpack2(acc[rp][2]), c3 = unpack2(acc[rp][3]);
        float vv[2][4] = { {c0.x, c1.x, c2.x, c3.x}, {c0.y, c1.y, c2.y, c3.y} };
#pragma unroll
        for (int h = 0; h < 2; h++) {
            int gr = r0b + ty * 8 + rp * 2 + h;
            float part = 0.f;
#pragma unroll
            for (int c4 = 0; c4 < 4; c4++)
                part += fmaxf(vv[h][c4] + bb1v[c4], 0.f) * wb2v[c4];
#pragma unroll
            for (int o = 8; o; o >>= 1)
                part += __shfl_xor_sync(0xFFFFFFFFu, part, o);
            if (gr < n) {
#pragma unroll
                for (int c4 = 0; c4 < 4; c4++) {
                    int c = tx * 4 + c4;
                    if (c < 10) optO[gr * 10 + c] = vv[h][c4] + boptv[c4];
                }
                if (tx == 0)
                    botO[gr] = 1.f / (1.f + __expf(-(part + bb2v)));
            }
        }
    }

    __syncthreads();
    if (t < 64) atomicAdd(&geO[t], sge[t] * invn);
}

// ---------------- GCN aggregation (round-9 loop shape, fp16 gathers) --------
// lane owns col pair (2*lane, 2*lane+1); one half2 (4B) per edge per lane.
__global__ void k_gcn_agg(const __half* __restrict__ t, const float* __restrict__ bias,
                          float* __restrict__ out, int n) {
    int w = (blockIdx.x * blockDim.x + threadIdx.x) >> 5;
    int lane = threadIdx.x & 31;
    if (w >= n) return;
    const uint* __restrict__ T = (const uint*)t;
    int s0 = g_rowptr[w], s1 = g_rowptr[w + 1];
    float2 acc = h2f(T[w * 32 + lane]);      // self-loop (pre-scaled)
    int e = s0;
    for (; e + 3 < s1; e += 4) {             // 4 independent loads in flight
        int i0 = g_csrc[e], i1 = g_csrc[e + 1], i2 = g_csrc[e + 2], i3 = g_csrc[e + 3];
        uint v0 = T[i0 * 32 + lane], v1 = T[i1 * 32 + lane];
        uint v2 = T[i2 * 32 + lane], v3 = T[i3 * 32 + lane];
        float2 f0 = h2f(v0), f1 = h2f(v1), f2 = h2f(v2), f3 = h2f(v3);
        acc.x += f0.x + f1.x; acc.y += f0.y + f1.y;
        acc.x += f2.x + f3.x; acc.y += f2.y + f3.y;
    }
    for (; e < s1; e++) {
        float2 f = h2f(T[g_csrc[e] * 32 + lane]);
        acc.x += f.x; acc.y += f.y;
    }
    float di = g_dinv[w];
    float2 bp = *(const float2*)&bias[lane * 2];
    float2 o = make_float2(fmaxf(acc.x * di + bp.x, 0.f), fmaxf(acc.y * di + bp.y, 0.f));
    *(float2*)&out[w * 64 + lane * 2] = o;
}

// ---------------- GAT aggregation (re-zeroes g_deg; fp16 feature gathers) ---
__global__ void k_gat(const __half* __restrict__ t, const float* __restrict__ bias,
                      float* __restrict__ out, int n) {
    int gid = blockIdx.x * blockDim.x + threadIdx.x;
    if (gid < n) g_deg[gid] = 0;   // consumed by scan; reset for next replay
    int w = gid >> 5;
    int lane = threadIdx.x & 31;
    if (w >= n) return;
    const uint* __restrict__ T = (const uint*)t;
    int s0 = g_rowptr[w], s1 = g_rowptr[w + 1];
    int deg = s1 - s0;
    float adi = g_ad[w];
    float eself = leaky(g_as[w] + adi);
    float2 acc = make_float2(0.f, 0.f);

    if (deg <= 128) {
        int cs[4];
        float pv[4];
        float m = eself;
#pragma unroll
        for (int j = 0; j < 4; j++) {
            int e = s0 + j * 32 + lane;
            if (e < s1) {
                int s = g_csrc[e];
                cs[j] = s;
                float v = leaky(g_as[s] + adi);
                pv[j] = v;
                m = fmaxf(m, v);
            } else { cs[j] = 0; pv[j] = -1e30f; }
        }
#pragma unroll
        for (int o = 16; o; o >>= 1) m = fmaxf(m, __shfl_xor_sync(0xFFFFFFFFu, m, o));

        float sum = 0.f;
#pragma unroll
        for (int j = 0; j < 4; j++) {
            pv[j] = __expf(pv[j] - m);   // inactive lanes underflow to 0
            sum += pv[j];
        }
#pragma unroll
        for (int o = 16; o; o >>= 1) sum += __shfl_xor_sync(0xFFFFFFFFu, sum, o);
        float es = __expf(eself - m);
        float inv = 1.f / (sum + es);

        {
            float ps = es * inv;
            float2 sv = h2f(T[w * 32 + lane]);
            acc.x = sv.x * ps; acc.y = sv.y * ps;
        }

#pragma unroll
        for (int j = 0; j < 4; j++) {
            int base = s0 + j * 32;
            if (base >= s1) break;
            int cnt = min(32, s1 - base);
            int l = 0;
            for (; l + 1 < cnt; l += 2) {
                int   sA = __shfl_sync(0xFFFFFFFFu, cs[j], l);
                int   sB = __shfl_sync(0xFFFFFFFFu, cs[j], l + 1);
                float pA = __shfl_sync(0xFFFFFFFFu, pv[j], l) * inv;
                float pB = __shfl_sync(0xFFFFFFFFu, pv[j], l + 1) * inv;
                uint vA = T[sA * 32 + lane], vB = T[sB * 32 + lane];
                float2 fA = h2f(vA), fB = h2f(vB);
                acc.x = fmaf(fA.x, pA, acc.x); acc.y = fmaf(fA.y, pA, acc.y);
                acc.x = fmaf(fB.x, pB, acc.x); acc.y = fmaf(fB.y, pB, acc.y);
            }
            if (l < cnt) {
                int   sA = __shfl_sync(0xFFFFFFFFu, cs[j], l);
                float pA = __shfl_sync(0xFFFFFFFFu, pv[j], l) * inv;
                float2 fA = h2f(T[sA * 32 + lane]);
                acc.x = fmaf(fA.x, pA, acc.x); acc.y = fmaf(fA.y, pA, acc.y);
            }
        }
    } else {
        // fallback: 3-pass via g_p (deg > 128)
        float m = eself;
        for (int e = s0 + lane; e < s1; e += 32) {
            float v = leaky(g_as[g_csrc[e]] + adi);
            g_p[e] = v;
            m = fmaxf(m, v);
        }
#pragma unroll
        for (int o = 16; o; o >>= 1) m = fmaxf(m, __shfl_xor_sync(0xFFFFFFFFu, m, o));
        float sum = 0.f;
        for (int e = s0 + lane; e < s1; e += 32) {
            float pe = __expf(g_p[e] - m);
            g_p[e] = pe;
            sum += pe;
        }
#pragma unroll
        for (int o = 16; o; o >>= 1) sum += __shfl_xor_sync(0xFFFFFFFFu, sum, o);
        float es = __expf(eself - m);
        float inv = 1.f / (sum + es);
        float ps = es * inv;
        float2 sv = h2f(T[w * 32 + lane]);
        acc.x = sv.x * ps; acc.y = sv.y * ps;
        for (int e = s0; e < s1; e++) {
            int sA = g_csrc[e];
            float aA = g_p[e] * inv;
            float2 f = h2f(T[sA * 32 + lane]);
            acc.x = fmaf(f.x, aA, acc.x); acc.y = fmaf(f.y, aA, acc.y);
        }
    }
    float2 bp = *(const float2*)&bias[lane * 2];
    float2 o = make_float2(fmaxf(acc.x + bp.x, 0.f), fmaxf(acc.y + bp.y, 0.f));
    *(float2*)&out[w * 64 + lane * 2] = o;
}

// ---------------- launcher ----------------
extern "C" void kernel_launch(void* const* d_in, const int* in_sizes, int n_in,
                              void* d_out, int out_size) {
    const float* x     = (const float*)d_in[0];
    const int*   ei    = (const int*)d_in[1];
    const float* W1    = (const float*)d_in[2];
    const float* b1    = (const float*)d_in[3];
    const float* W2    = (const float*)d_in[4];
    const float* a_src = (const float*)d_in[5];
    const float* a_dst = (const float*)d_in[6];
    const float* b2    = (const float*)d_in[7];
    const float* W3    = (const float*)d_in[8];
    const float* b3    = (const float*)d_in[9];
    const float* Wopt  = (const float*)d_in[10];
    const float* bopt  = (const float*)d_in[11];
    const float* Wb1   = (const float*)d_in[12];
    const float* bb1   = (const float*)d_in[13];
    const float* Wb2   = (const float*)d_in[14];
    const float* bb2   = (const float*)d_in[15];

    int n = in_sizes[0] / 32;
    int e = in_sizes[1] / 2;
    const int* src = ei;
    const int* dst = ei + e;

    float* out  = (float*)d_out;
    float* optO = out;
    float* botO = out + (size_t)n * 10;
    float* geO  = botO + n;

    __half* p_t;
    float *p_h, *p_wc;
    cudaGetSymbolAddress((void**)&p_t, g_t);
    cudaGetSymbolAddress((void**)&p_h, g_h);
    cudaGetSymbolAddress((void**)&p_wc, g_wc);

    int eb256  = (e + 255) / 256;
    int warpsB = (n + 7) / 8;
    int gemmB  = (n + 127) / 128;
    int scanB  = (n + 1023) / 1024;

    // structure: count (+ init extras) -> one-kernel scan -> fill (+gemm1)
    k_count_init<<<eb256 + 17, 256>>>(dst, e, eb256, geO, Wopt, Wb1);
    k_scan_one<<<scanB, 256>>>(n, e);
    k_fill_gemm<<<eb256 + gemmB, 256>>>(src, dst, e, eb256, x, W1, p_t, n);

    // layer 1: GCN aggregation + relu
    k_gcn_agg<<<warpsB, 256>>>(p_t, b1, p_h, n);

    // layer 2: GAT(64->64) + relu (GEMM epilogue emits alpha_src/alpha_dst)
    k_gemm128<64, 2><<<gemmB, 256>>>(p_h, W2, p_t, n, a_src, a_dst);
    k_gat<<<warpsB, 256>>>(p_t, b2, p_h, n);

    // layer 3: GCN(64->64) + relu
    k_gemm128<64, 1><<<gemmB, 256>>>(p_h, W3, p_t, n, nullptr, nullptr);
    k_gcn_agg<<<warpsB, 256>>>(p_t, b3, p_h, n);

    // heads: GEMM with packed [Wopt|Wb1] + fully fused epilogue
    k_gemm_head<<<gemmB, 256>>>(p_h, p_wc, n, bopt, bb1, Wb2, bb2,
                                optO, botO, geO, 1.0f / (float)n);
}

// round 15
// speedup vs baseline: 1.1782x; 1.0381x over previous
#include <cuda_runtime.h>
#include <cuda_fp16.h>
#include <math.h>

#define NMAX 100000
#define EMAX 1250000
#define HDIM 64
#define SCAN_READY (1 << 30)

typedef unsigned long long ull;
typedef unsigned int uint;

// ---------------- scratch (static device globals; no allocs) ----------------
__device__ __align__(16) __half g_t[NMAX * HDIM];   // fp16 gathered intermediate
__device__ __align__(16) float g_h[NMAX * HDIM];
__device__ __align__(16) int   g_deg[NMAX];
__device__ float g_dinv[NMAX];
__device__ int   g_rowptr[NMAX + 1];
__device__ int   g_fill[NMAX];
__device__ int   g_csrc[EMAX];
__device__ float g_as[NMAX];
__device__ float g_ad[NMAX];
__device__ float g_p[EMAX];          // fallback path only (deg > 128)
__device__ __align__(16) float g_wc[64 * 64];
__device__ int   g_bsum[128];

__device__ __forceinline__ float leaky(float v) { return v > 0.f ? v : 0.2f * v; }

__device__ __forceinline__ void ffma2(ull& acc, ull a, ull b) {
    asm("fma.rn.f32x2 %0, %1, %2, %0;" : "+l"(acc) : "l"(a), "l"(b));
}
__device__ __forceinline__ ull pack2(float lo, float hi) {
    ull r;
    asm("mov.b64 %0, {%1, %2};" : "=l"(r) : "f"(lo), "f"(hi));
    return r;
}
__device__ __forceinline__ float2 unpack2(ull v) {
    float2 r;
    asm("mov.b64 {%0, %1}, %2;" : "=f"(r.x), "=f"(r.y) : "l"(v));
    return r;
}
// half2 (as uint) -> float2
__device__ __forceinline__ float2 h2f(uint v) {
    __half2 h = *reinterpret_cast<__half2*>(&v);
    return __half22float2(h);
}
__device__ __forceinline__ uint f2h(float a, float b) {
    __half2 h = __float22half2_rn(make_float2(a, b));
    return *reinterpret_cast<uint*>(&h);
}
// fp16 pairwise add of two half2 words (HADD2)
__device__ __forceinline__ uint hadd2u(uint a, uint b) {
    __half2 r = __hadd2(*reinterpret_cast<__half2*>(&a),
                        *reinterpret_cast<__half2*>(&b));
    return *reinterpret_cast<uint*>(&r);
}

// ---------------- count + init (geO zero, bsum flags zero, packed Wc) -------
__global__ void k_count_init(const int* __restrict__ dst, int e, int ebN,
                             float* __restrict__ geO,
                             const float* __restrict__ Wopt,
                             const float* __restrict__ Wb1) {
    int b = blockIdx.x;
    if (b < ebN) {
        int i = b * 256 + threadIdx.x;
        if (i < e) atomicAdd(&g_deg[dst[i]], 1);
        return;
    }
    int i = (b - ebN) * 256 + threadIdx.x;
    if (i < 64) geO[i] = 0.f;
    if (i < 128) g_bsum[i] = 0;
    if (i < 4096) {
        int k = i >> 6, c = i & 63;
        float v = 0.f;
        if (c < 10) v = Wopt[k * 10 + c];
        else if (c < 42) v = Wb1[k * 32 + (c - 10)];
        g_wc[i] = v;
    }
}

// ------------- single-pass exclusive scan with parallel lookback ------------
__global__ void k_scan_one(int n, int e) {
    __shared__ int sm[256];
    __shared__ int sl[256];
    int b = blockIdx.x, t = threadIdx.x;
    int base = b * 1024 + t * 4;
    int d[4];
    int s = 0;
#pragma unroll
    for (int j = 0; j < 4; j++) {
        int i = base + j;
        d[j] = (i < n) ? g_deg[i] : 0;
        s += d[j];
    }
    sm[t] = s;
    __syncthreads();
#pragma unroll
    for (int off = 1; off < 256; off <<= 1) {
        int v = (t >= off) ? sm[t - off] : 0;
        __syncthreads();
        sm[t] += v;
        __syncthreads();
    }
    if (t == 0) atomicExch(&g_bsum[b], sm[255] | SCAN_READY);

    int part = 0;
    if (t < b) {
        volatile int* vb = g_bsum;
        int v;
        do { v = vb[t]; } while (!(v & SCAN_READY));
        part = v & (SCAN_READY - 1);
    }
    sl[t] = part;
    __syncthreads();
#pragma unroll
    for (int off = 128; off; off >>= 1) {
        if (t < off) sl[t] += sl[t + off];
        __syncthreads();
    }
    int run = sl[0] + sm[t] - s;
#pragma unroll
    for (int j = 0; j < 4; j++) {
        int i = base + j;
        if (i < n) {
            g_rowptr[i] = run;
            g_fill[i] = run;
            g_dinv[i] = rsqrtf((float)(d[j] + 1));  // +1 self-loop
            run += d[j];
        }
    }
    if (b == 0 && t == 0) g_rowptr[n] = e;
}

// ---------------- GEMM body: C[n,64](fp16) = A[n,K](fp32) @ B[K,64] ---------
// EPI: 0 plain | 1 scale row by g_dinv[row] | 2 also emit g_as/g_ad
template <int K, int EPI>
__device__ __forceinline__ void gemm_body(const float* __restrict__ A,
                                          const float* __restrict__ B,
                                          __half* __restrict__ C, int n, int bid,
                                          const float* __restrict__ av1,
                                          const float* __restrict__ av2) {
    constexpr int KT = (K > 32) ? 32 : K;
    __shared__ __align__(16) float As[KT][132];
    __shared__ __align__(16) float Bs[K][64];
    int t = threadIdx.x;
    int r0b = bid * 128;
    int tx = t & 15, ty = t >> 4;

#pragma unroll
    for (int j = 0; j < (K * 64) / 256; j++) {
        int idx = t + j * 256;
        Bs[idx >> 6][idx & 63] = B[idx];
    }

    ull acc[4][4] = {};

    for (int kt = 0; kt < K; kt += KT) {
        __syncthreads();
#pragma unroll
        for (int j = 0; j < (KT * 128) / 256; j++) {
            int idx = t + j * 256;
            int r = idx / KT, k = idx % KT;
            int gr = r0b + r;
            As[k][r] = (gr < n) ? A[gr * K + kt + k] : 0.f;
        }
        __syncthreads();
#pragma unroll
        for (int kk = 0; kk < KT; kk++) {
            float4 bq = *(const float4*)&Bs[kt + kk][tx * 4];
            ull b0 = pack2(bq.x, bq.x), b1 = pack2(bq.y, bq.y);
            ull b2 = pack2(bq.z, bq.z), b3 = pack2(bq.w, bq.w);
            ulonglong2 aA = *(const ulonglong2*)&As[kk][ty * 8];
            ulonglong2 aB = *(const ulonglong2*)&As[kk][ty * 8 + 4];
            ffma2(acc[0][0], aA.x, b0); ffma2(acc[0][1], aA.x, b1);
            ffma2(acc[0][2], aA.x, b2); ffma2(acc[0][3], aA.x, b3);
            ffma2(acc[1][0], aA.y, b0); ffma2(acc[1][1], aA.y, b1);
            ffma2(acc[1][2], aA.y, b2); ffma2(acc[1][3], aA.y, b3);
            ffma2(acc[2][0], aB.x, b0); ffma2(acc[2][1], aB.x, b1);
            ffma2(acc[2][2], aB.x, b2); ffma2(acc[2][3], aB.x, b3);
            ffma2(acc[3][0], aB.y, b0); ffma2(acc[3][1], aB.y, b1);
            ffma2(acc[3][2], aB.y, b2); ffma2(acc[3][3], aB.y, b3);
        }
    }

    float4 as4, ad4;
    if (EPI == 2) {
        as4 = *(const float4*)&av1[tx * 4];
        ad4 = *(const float4*)&av2[tx * 4];
    }
#pragma unroll
    for (int rp = 0; rp < 4; rp++) {
        float2 c0 = unpack2(acc[rp][0]), c1 = unpack2(acc[rp][1]);
        float2 c2 = unpack2(acc[rp][2]), c3 = unpack2(acc[rp][3]);
        float4 v[2] = { make_float4(c0.x, c1.x, c2.x, c3.x),
                        make_float4(c0.y, c1.y, c2.y, c3.y) };
#pragma unroll
        for (int h = 0; h < 2; h++) {
            int gr = r0b + ty * 8 + rp * 2 + h;
            float4 cv = v[h];
            if (EPI == 1 && gr < n) {
                float s = g_dinv[gr];
                cv.x *= s; cv.y *= s; cv.z *= s; cv.w *= s;
            }
            if (gr < n) {
                uint2 st = make_uint2(f2h(cv.x, cv.y), f2h(cv.z, cv.w));
                *(uint2*)&C[gr * 64 + tx * 4] = st;   // STG.64, fp16 row
            }
            if (EPI == 2) {
                float ps = cv.x * as4.x + cv.y * as4.y + cv.z * as4.z + cv.w * as4.w;
                float pd = cv.x * ad4.x + cv.y * ad4.y + cv.z * ad4.z + cv.w * ad4.w;
#pragma unroll
                for (int o = 8; o; o >>= 1) {
                    ps += __shfl_xor_sync(0xFFFFFFFFu, ps, o);
                    pd += __shfl_xor_sync(0xFFFFFFFFu, pd, o);
                }
                if (tx == 0 && gr < n) { g_as[gr] = ps; g_ad[gr] = pd; }
            }
        }
    }
}

template <int K, int EPI>
__global__ __launch_bounds__(256) void k_gemm128(const float* __restrict__ A,
                                                 const float* __restrict__ B,
                                                 __half* __restrict__ C, int n,
                                                 const float* __restrict__ av1,
                                                 const float* __restrict__ av2) {
    gemm_body<K, EPI>(A, B, C, n, blockIdx.x, av1, av2);
}

// ---------------- fused: CSR fill blocks + layer-1 GEMM blocks ---------------
__global__ __launch_bounds__(256) void k_fill_gemm(const int* __restrict__ src,
                                                   const int* __restrict__ dst,
                                                   int e, int ebN,
                                                   const float* __restrict__ A,
                                                   const float* __restrict__ B,
                                                   __half* __restrict__ C, int n) {
    if ((int)blockIdx.x < ebN) {
        int i = blockIdx.x * 256 + threadIdx.x;
        if (i < e) {
            int d = dst[i];
            int p = atomicAdd(&g_fill[d], 1);
            g_csrc[p] = src[i];
        }
        return;
    }
    gemm_body<32, 1>(A, B, C, n, blockIdx.x - ebN, nullptr, nullptr);
}

// ---------------- head GEMM + fused epilogue (fp32 A = h3, no tc buffer) ----
__global__ __launch_bounds__(256) void k_gemm_head(const float* __restrict__ A,
                                                   const float* __restrict__ B,
                                                   int n,
                                                   const float* __restrict__ bopt,
                                                   const float* __restrict__ bb1,
                                                   const float* __restrict__ Wb2,
                                                   const float* __restrict__ bb2,
                                                   float* __restrict__ optO,
                                                   float* __restrict__ botO,
                                                   float* __restrict__ geO,
                                                   float invn) {
    constexpr int K = 64, KT = 32;
    __shared__ __align__(16) float As[KT][132];
    __shared__ __align__(16) float Bs[K][64];
    __shared__ float sge[64];
    int t = threadIdx.x;
    int r0b = blockIdx.x * 128;
    int tx = t & 15, ty = t >> 4;

    if (t < 64) sge[t] = 0.f;
#pragma unroll
    for (int j = 0; j < (K * 64) / 256; j++) {
        int idx = t + j * 256;
        Bs[idx >> 6][idx & 63] = B[idx];
    }

    ull acc[4][4] = {};

    for (int kt = 0; kt < K; kt += KT) {
        __syncthreads();
#pragma unroll
        for (int j = 0; j < (KT * 128) / 256; j++) {
            int idx = t + j * 256;
            int r = idx / KT, k = idx % KT;
            int gr = r0b + r;
            As[k][r] = (gr < n) ? A[gr * K + kt + k] : 0.f;
        }
        __syncthreads();
        {
            int kk = t & 31, r0 = (t >> 5) * 16;
            float gp = 0.f;
#pragma unroll
            for (int r = 0; r < 16; r++) gp += As[kk][r0 + r];
            atomicAdd(&sge[kt + kk], gp);
        }
#pragma unroll
        for (int kk = 0; kk < KT; kk++) {
            float4 bq = *(const float4*)&Bs[kt + kk][tx * 4];
            ull b0 = pack2(bq.x, bq.x), b1 = pack2(bq.y, bq.y);
            ull b2 = pack2(bq.z, bq.z), b3 = pack2(bq.w, bq.w);
            ulonglong2 aA = *(const ulonglong2*)&As[kk][ty * 8];
            ulonglong2 aB = *(const ulonglong2*)&As[kk][ty * 8 + 4];
            ffma2(acc[0][0], aA.x, b0); ffma2(acc[0][1], aA.x, b1);
            ffma2(acc[0][2], aA.x, b2); ffma2(acc[0][3], aA.x, b3);
            ffma2(acc[1][0], aA.y, b0); ffma2(acc[1][1], aA.y, b1);
            ffma2(acc[1][2], aA.y, b2); ffma2(acc[1][3], aA.y, b3);
            ffma2(acc[2][0], aB.x, b0); ffma2(acc[2][1], aB.x, b1);
            ffma2(acc[2][2], aB.x, b2); ffma2(acc[2][3], aB.x, b3);
            ffma2(acc[3][0], aB.y, b0); ffma2(acc[3][1], aB.y, b1);
            ffma2(acc[3][2], aB.y, b2); ffma2(acc[3][3], aB.y, b3);
        }
    }

    float bb2v = bb2[0];
    float boptv[4], bb1v[4], wb2v[4];
#pragma unroll
    for (int c4 = 0; c4 < 4; c4++) {
        int c = tx * 4 + c4;
        boptv[c4] = (c < 10) ? bopt[c] : 0.f;
        bb1v[c4]  = (c >= 10 && c < 42) ? bb1[c - 10] : 0.f;
        wb2v[c4]  = (c >= 10 && c < 42) ? Wb2[c - 10] : 0.f;
    }

#pragma unroll
    for (int rp = 0; rp < 4; rp++) {
        float2 c0 = unpack2(acc[rp][0]), c1 = unpack2(acc[rp][1]);
        float2 c2 = unpack2(acc[rp][2]), c3 = unpack2(acc[rp][3]);
        float vv[2][4] = { {c0.x, c1.x, c2.x, c3.x}, {c0.y, c1.y, c2.y, c3.y} };
#pragma unroll
        for (int h = 0; h < 2; h++) {
            int gr = r0b + ty * 8 + rp * 2 + h;
            float part = 0.f;
#pragma unroll
            for (int c4 = 0; c4 < 4; c4++)
                part += fmaxf(vv[h][c4] + bb1v[c4], 0.f) * wb2v[c4];
#pragma unroll
            for (int o = 8; o; o >>= 1)
                part += __shfl_xor_sync(0xFFFFFFFFu, part, o);
            if (gr < n) {
#pragma unroll
                for (int c4 = 0; c4 < 4; c4++) {
                    int c = tx * 4 + c4;
                    if (c < 10) optO[gr * 10 + c] = vv[h][c4] + boptv[c4];
                }
                if (tx == 0)
                    botO[gr] = 1.f / (1.f + __expf(-(part + bb2v)));
            }
        }
    }

    __syncthreads();
    if (t < 64) atomicAdd(&geO[t], sge[t] * invn);
}

// ---------------- GCN aggregation (fp16 gathers, HADD2 pairwise combine) ----
// lane owns col pair (2*lane, 2*lane+1); edge pairs pre-summed in fp16.
__global__ void k_gcn_agg(const __half* __restrict__ t, const float* __restrict__ bias,
                          float* __restrict__ out, int n) {
    int w = (blockIdx.x * blockDim.x + threadIdx.x) >> 5;
    int lane = threadIdx.x & 31;
    if (w >= n) return;
    const uint* __restrict__ T = (const uint*)t;
    int s0 = g_rowptr[w], s1 = g_rowptr[w + 1];
    float2 acc = h2f(T[w * 32 + lane]);      // self-loop (pre-scaled)
    int e = s0;
    for (; e + 3 < s1; e += 4) {             // 4 independent loads in flight
        int i0 = g_csrc[e], i1 = g_csrc[e + 1], i2 = g_csrc[e + 2], i3 = g_csrc[e + 3];
        uint v0 = T[i0 * 32 + lane], v1 = T[i1 * 32 + lane];
        uint v2 = T[i2 * 32 + lane], v3 = T[i3 * 32 + lane];
        uint h01 = hadd2u(v0, v1);           // fp16 pairwise (HADD2)
        uint h23 = hadd2u(v2, v3);
        float2 f01 = h2f(h01), f23 = h2f(h23);
        acc.x += f01.x + f23.x;
        acc.y += f01.y + f23.y;
    }
    if (e + 1 < s1) {
        int i0 = g_csrc[e], i1 = g_csrc[e + 1];
        uint h01 = hadd2u(T[i0 * 32 + lane], T[i1 * 32 + lane]);
        float2 f = h2f(h01);
        acc.x += f.x; acc.y += f.y;
        e += 2;
    }
    if (e < s1) {
        float2 f = h2f(T[g_csrc[e] * 32 + lane]);
        acc.x += f.x; acc.y += f.y;
    }
    float di = g_dinv[w];
    float2 bp = *(const float2*)&bias[lane * 2];
    float2 o = make_float2(fmaxf(acc.x * di + bp.x, 0.f), fmaxf(acc.y * di + bp.y, 0.f));
    *(float2*)&out[w * 64 + lane * 2] = o;
}

// ---------------- GAT aggregation (re-zeroes g_deg; fp16 feature gathers) ---
__global__ void k_gat(const __half* __restrict__ t, const float* __restrict__ bias,
                      float* __restrict__ out, int n) {
    int gid = blockIdx.x * blockDim.x + threadIdx.x;
    if (gid < n) g_deg[gid] = 0;   // consumed by scan; reset for next replay
    int w = gid >> 5;
    int lane = threadIdx.x & 31;
    if (w >= n) return;
    const uint* __restrict__ T = (const uint*)t;
    int s0 = g_rowptr[w], s1 = g_rowptr[w + 1];
    int deg = s1 - s0;
    float adi = g_ad[w];
    float eself = leaky(g_as[w] + adi);
    float2 acc = make_float2(0.f, 0.f);

    if (deg <= 128) {
        int cs[4];
        float pv[4];
        float m = eself;
#pragma unroll
        for (int j = 0; j < 4; j++) {
            int e = s0 + j * 32 + lane;
            if (e < s1) {
                int s = g_csrc[e];
                cs[j] = s;
                float v = leaky(g_as[s] + adi);
                pv[j] = v;
                m = fmaxf(m, v);
            } else { cs[j] = 0; pv[j] = -1e30f; }
        }
#pragma unroll
        for (int o = 16; o; o >>= 1) m = fmaxf(m, __shfl_xor_sync(0xFFFFFFFFu, m, o));

        float sum = 0.f;
#pragma unroll
        for (int j = 0; j < 4; j++) {
            pv[j] = __expf(pv[j] - m);   // inactive lanes underflow to 0
            sum += pv[j];
        }
#pragma unroll
        for (int o = 16; o; o >>= 1) sum += __shfl_xor_sync(0xFFFFFFFFu, sum, o);
        float es = __expf(eself - m);
        float inv = 1.f / (sum + es);

        {
            float ps = es * inv;
            float2 sv = h2f(T[w * 32 + lane]);
            acc.x = sv.x * ps; acc.y = sv.y * ps;
        }

#pragma unroll
        for (int j = 0; j < 4; j++) {
            int base = s0 + j * 32;
            if (base >= s1) break;
            int cnt = min(32, s1 - base);
            int l = 0;
            for (; l + 1 < cnt; l += 2) {
                int   sA = __shfl_sync(0xFFFFFFFFu, cs[j], l);
                int   sB = __shfl_sync(0xFFFFFFFFu, cs[j], l + 1);
                float pA = __shfl_sync(0xFFFFFFFFu, pv[j], l) * inv;
                float pB = __shfl_sync(0xFFFFFFFFu, pv[j], l + 1) * inv;
                uint vA = T[sA * 32 + lane], vB = T[sB * 32 + lane];
                float2 fA = h2f(vA), fB = h2f(vB);
                acc.x = fmaf(fA.x, pA, acc.x); acc.y = fmaf(fA.y, pA, acc.y);
                acc.x = fmaf(fB.x, pB, acc.x); acc.y = fmaf(fB.y, pB, acc.y);
            }
            if (l < cnt) {
                int   sA = __shfl_sync(0xFFFFFFFFu, cs[j], l);
                float pA = __shfl_sync(0xFFFFFFFFu, pv[j], l) * inv;
                float2 fA = h2f(T[sA * 32 + lane]);
                acc.x = fmaf(fA.x, pA, acc.x); acc.y = fmaf(fA.y, pA, acc.y);
            }
        }
    } else {
        // fallback: 3-pass via g_p (deg > 128)
        float m = eself;
        for (int e = s0 + lane; e < s1; e += 32) {
            float v = leaky(g_as[g_csrc[e]] + adi);
            g_p[e] = v;
            m = fmaxf(m, v);
        }
#pragma unroll
        for (int o = 16; o; o >>= 1) m = fmaxf(m, __shfl_xor_sync(0xFFFFFFFFu, m, o));
        float sum = 0.f;
        for (int e = s0 + lane; e < s1; e += 32) {
            float pe = __expf(g_p[e] - m);
            g_p[e] = pe;
            sum += pe;
        }
#pragma unroll
        for (int o = 16; o; o >>= 1) sum += __shfl_xor_sync(0xFFFFFFFFu, sum, o);
        float es = __expf(eself - m);
        float inv = 1.f / (sum + es);
        float ps = es * inv;
        float2 sv = h2f(T[w * 32 + lane]);
        acc.x = sv.x * ps; acc.y = sv.y * ps;
        for (int e = s0; e < s1; e++) {
            int sA = g_csrc[e];
            float aA = g_p[e] * inv;
            float2 f = h2f(T[sA * 32 + lane]);
            acc.x = fmaf(f.x, aA, acc.x); acc.y = fmaf(f.y, aA, acc.y);
        }
    }
    float2 bp = *(const float2*)&bias[lane * 2];
    float2 o = make_float2(fmaxf(acc.x + bp.x, 0.f), fmaxf(acc.y + bp.y, 0.f));
    *(float2*)&out[w * 64 + lane * 2] = o;
}

// ---------------- launcher ----------------
extern "C" void kernel_launch(void* const* d_in, const int* in_sizes, int n_in,
                              void* d_out, int out_size) {
    const float* x     = (const float*)d_in[0];
    const int*   ei    = (const int*)d_in[1];
    const float* W1    = (const float*)d_in[2];
    const float* b1    = (const float*)d_in[3];
    const float* W2    = (const float*)d_in[4];
    const float* a_src = (const float*)d_in[5];
    const float* a_dst = (const float*)d_in[6];
    const float* b2    = (const float*)d_in[7];
    const float* W3    = (const float*)d_in[8];
    const float* b3    = (const float*)d_in[9];
    const float* Wopt  = (const float*)d_in[10];
    const float* bopt  = (const float*)d_in[11];
    const float* Wb1   = (const float*)d_in[12];
    const float* bb1   = (const float*)d_in[13];
    const float* Wb2   = (const float*)d_in[14];
    const float* bb2   = (const float*)d_in[15];

    int n = in_sizes[0] / 32;
    int e = in_sizes[1] / 2;
    const int* src = ei;
    const int* dst = ei + e;

    float* out  = (float*)d_out;
    float* optO = out;
    float* botO = out + (size_t)n * 10;
    float* geO  = botO + n;

    __half* p_t;
    float *p_h, *p_wc;
    cudaGetSymbolAddress((void**)&p_t, g_t);
    cudaGetSymbolAddress((void**)&p_h, g_h);
    cudaGetSymbolAddress((void**)&p_wc, g_wc);

    int eb256  = (e + 255) / 256;
    int warpsB = (n + 7) / 8;
    int gemmB  = (n + 127) / 128;
    int scanB  = (n + 1023) / 1024;

    // structure: count (+ init extras) -> one-kernel scan -> fill (+gemm1)
    k_count_init<<<eb256 + 17, 256>>>(dst, e, eb256, geO, Wopt, Wb1);
    k_scan_one<<<scanB, 256>>>(n, e);
    k_fill_gemm<<<eb256 + gemmB, 256>>>(src, dst, e, eb256, x, W1, p_t, n);

    // layer 1: GCN aggregation + relu
    k_gcn_agg<<<warpsB, 256>>>(p_t, b1, p_h, n);

    // layer 2: GAT(64->64) + relu (GEMM epilogue emits alpha_src/alpha_dst)
    k_gemm128<64, 2><<<gemmB, 256>>>(p_h, W2, p_t, n, a_src, a_dst);
    k_gat<<<warpsB, 256>>>(p_t, b2, p_h, n);

    // layer 3: GCN(64->64) + relu
    k_gemm128<64, 1><<<gemmB, 256>>>(p_h, W3, p_t, n, nullptr, nullptr);
    k_gcn_agg<<<warpsB, 256>>>(p_t, b3, p_h, n);

    // heads: GEMM with packed [Wopt|Wb1] + fully fused epilogue
    k_gemm_head<<<gemmB, 256>>>(p_h, p_wc, n, bopt, bb1, Wb2, bb2,
                                optO, botO, geO, 1.0f / (float)n);
}

// round 16
// speedup vs baseline: 1.2039x; 1.0218x over previous
#include <cuda_runtime.h>
#include <cuda_fp16.h>
#include <math.h>

#define NMAX 100000
#define EMAX 1250000
#define HDIM 64
#define SCAN_READY (1 << 30)

typedef unsigned long long ull;
typedef unsigned int uint;

// ---------------- scratch (static device globals; no allocs) ----------------
__device__ __align__(16) __half g_t[NMAX * HDIM];   // fp16 gathered intermediate
__device__ __align__(16) float g_h[NMAX * HDIM];
__device__ __align__(16) int   g_deg[NMAX];
__device__ float g_dinv[NMAX];
__device__ int   g_rowptr[NMAX + 1];
__device__ int   g_fill[NMAX];
__device__ int   g_csrc[EMAX];
__device__ float g_as[NMAX];
__device__ float g_ad[NMAX];
__device__ float g_p[EMAX];          // fallback path only (deg > 128)
__device__ __align__(16) float g_wc[64 * 64];
__device__ int   g_bsum[128];

__device__ __forceinline__ float leaky(float v) { return v > 0.f ? v : 0.2f * v; }

__device__ __forceinline__ void pdl_sync() {
#if defined(__CUDA_ARCH__) && (__CUDA_ARCH__ >= 900)
    cudaGridDependencySynchronize();
#endif
}

__device__ __forceinline__ void ffma2(ull& acc, ull a, ull b) {
    asm("fma.rn.f32x2 %0, %1, %2, %0;" : "+l"(acc) : "l"(a), "l"(b));
}
__device__ __forceinline__ ull pack2(float lo, float hi) {
    ull r;
    asm("mov.b64 %0, {%1, %2};" : "=l"(r) : "f"(lo), "f"(hi));
    return r;
}
__device__ __forceinline__ float2 unpack2(ull v) {
    float2 r;
    asm("mov.b64 {%0, %1}, %2;" : "=f"(r.x), "=f"(r.y) : "l"(v));
    return r;
}
// half2 (as uint) -> float2
__device__ __forceinline__ float2 h2f(uint v) {
    __half2 h = *reinterpret_cast<__half2*>(&v);
    return __half22float2(h);
}
__device__ __forceinline__ uint f2h(float a, float b) {
    __half2 h = __float22half2_rn(make_float2(a, b));
    return *reinterpret_cast<uint*>(&h);
}
// fp16 pairwise add of two half2 words (HADD2)
__device__ __forceinline__ uint hadd2u(uint a, uint b) {
    __half2 r = __hadd2(*reinterpret_cast<__half2*>(&a),
                        *reinterpret_cast<__half2*>(&b));
    return *reinterpret_cast<uint*>(&r);
}

// ---------------- count + init (geO zero, bsum flags zero, packed Wc) -------
__global__ void k_count_init(const int* __restrict__ dst, int e, int ebN,
                             float* __restrict__ geO,
                             const float* __restrict__ Wopt,
                             const float* __restrict__ Wb1) {
    int b = blockIdx.x;
    if (b < ebN) {
        int i = b * 256 + threadIdx.x;
        if (i < e) atomicAdd(&g_deg[dst[i]], 1);
        return;
    }
    int i = (b - ebN) * 256 + threadIdx.x;
    if (i < 64) geO[i] = 0.f;
    if (i < 128) g_bsum[i] = 0;
    if (i < 4096) {
        int k = i >> 6, c = i & 63;
        float v = 0.f;
        if (c < 10) v = Wopt[k * 10 + c];
        else if (c < 42) v = Wb1[k * 32 + (c - 10)];
        g_wc[i] = v;
    }
}

// ------------- single-pass exclusive scan with parallel lookback ------------
__global__ void k_scan_one(int n, int e) {
    __shared__ int sm[256];
    __shared__ int sl[256];
    pdl_sync();                       // g_deg from k_count_init
    int b = blockIdx.x, t = threadIdx.x;
    int base = b * 1024 + t * 4;
    int d[4];
    int s = 0;
#pragma unroll
    for (int j = 0; j < 4; j++) {
        int i = base + j;
        d[j] = (i < n) ? g_deg[i] : 0;
        s += d[j];
    }
    sm[t] = s;
    __syncthreads();
#pragma unroll
    for (int off = 1; off < 256; off <<= 1) {
        int v = (t >= off) ? sm[t - off] : 0;
        __syncthreads();
        sm[t] += v;
        __syncthreads();
    }
    if (t == 0) atomicExch(&g_bsum[b], sm[255] | SCAN_READY);

    int part = 0;
    if (t < b) {
        volatile int* vb = g_bsum;
        int v;
        do { v = vb[t]; } while (!(v & SCAN_READY));
        part = v & (SCAN_READY - 1);
    }
    sl[t] = part;
    __syncthreads();
#pragma unroll
    for (int off = 128; off; off >>= 1) {
        if (t < off) sl[t] += sl[t + off];
        __syncthreads();
    }
    int run = sl[0] + sm[t] - s;
#pragma unroll
    for (int j = 0; j < 4; j++) {
        int i = base + j;
        if (i < n) {
            g_rowptr[i] = run;
            g_fill[i] = run;
            g_dinv[i] = rsqrtf((float)(d[j] + 1));  // +1 self-loop
            run += d[j];
        }
    }
    if (b == 0 && t == 0) g_rowptr[n] = e;
}

// ---------------- GEMM body: C[n,64](fp16) = A[n,K](fp32) @ B[K,64] ---------
// EPI: 0 plain | 1 scale row by g_dinv[row] | 2 also emit g_as/g_ad
// Weight (B) smem loads happen BEFORE pdl_sync (independent of predecessor).
template <int K, int EPI>
__device__ __forceinline__ void gemm_body(const float* __restrict__ A,
                                          const float* __restrict__ B,
                                          __half* __restrict__ C, int n, int bid,
                                          const float* __restrict__ av1,
                                          const float* __restrict__ av2) {
    constexpr int KT = (K > 32) ? 32 : K;
    __shared__ __align__(16) float As[KT][132];
    __shared__ __align__(16) float Bs[K][64];
    int t = threadIdx.x;
    int r0b = bid * 128;
    int tx = t & 15, ty = t >> 4;

#pragma unroll
    for (int j = 0; j < (K * 64) / 256; j++) {
        int idx = t + j * 256;
        Bs[idx >> 6][idx & 63] = B[idx];
    }

    pdl_sync();                       // A (and g_dinv) may come from predecessor

    ull acc[4][4] = {};

    for (int kt = 0; kt < K; kt += KT) {
        __syncthreads();
#pragma unroll
        for (int j = 0; j < (KT * 128) / 256; j++) {
            int idx = t + j * 256;
            int r = idx / KT, k = idx % KT;
            int gr = r0b + r;
            As[k][r] = (gr < n) ? A[gr * K + kt + k] : 0.f;
        }
        __syncthreads();
#pragma unroll
        for (int kk = 0; kk < KT; kk++) {
            float4 bq = *(const float4*)&Bs[kt + kk][tx * 4];
            ull b0 = pack2(bq.x, bq.x), b1 = pack2(bq.y, bq.y);
            ull b2 = pack2(bq.z, bq.z), b3 = pack2(bq.w, bq.w);
            ulonglong2 aA = *(const ulonglong2*)&As[kk][ty * 8];
            ulonglong2 aB = *(const ulonglong2*)&As[kk][ty * 8 + 4];
            ffma2(acc[0][0], aA.x, b0); ffma2(acc[0][1], aA.x, b1);
            ffma2(acc[0][2], aA.x, b2); ffma2(acc[0][3], aA.x, b3);
            ffma2(acc[1][0], aA.y, b0); ffma2(acc[1][1], aA.y, b1);
            ffma2(acc[1][2], aA.y, b2); ffma2(acc[1][3], aA.y, b3);
            ffma2(acc[2][0], aB.x, b0); ffma2(acc[2][1], aB.x, b1);
            ffma2(acc[2][2], aB.x, b2); ffma2(acc[2][3], aB.x, b3);
            ffma2(acc[3][0], aB.y, b0); ffma2(acc[3][1], aB.y, b1);
            ffma2(acc[3][2], aB.y, b2); ffma2(acc[3][3], aB.y, b3);
        }
    }

    float4 as4, ad4;
    if (EPI == 2) {
        as4 = *(const float4*)&av1[tx * 4];
        ad4 = *(const float4*)&av2[tx * 4];
    }
#pragma unroll
    for (int rp = 0; rp < 4; rp++) {
        float2 c0 = unpack2(acc[rp][0]), c1 = unpack2(acc[rp][1]);
        float2 c2 = unpack2(acc[rp][2]), c3 = unpack2(acc[rp][3]);
        float4 v[2] = { make_float4(c0.x, c1.x, c2.x, c3.x),
                        make_float4(c0.y, c1.y, c2.y, c3.y) };
#pragma unroll
        for (int h = 0; h < 2; h++) {
            int gr = r0b + ty * 8 + rp * 2 + h;
            float4 cv = v[h];
            if (EPI == 1 && gr < n) {
                float s = g_dinv[gr];
                cv.x *= s; cv.y *= s; cv.z *= s; cv.w *= s;
            }
            if (gr < n) {
                uint2 st = make_uint2(f2h(cv.x, cv.y), f2h(cv.z, cv.w));
                *(uint2*)&C[gr * 64 + tx * 4] = st;   // STG.64, fp16 row
            }
            if (EPI == 2) {
                float ps = cv.x * as4.x + cv.y * as4.y + cv.z * as4.z + cv.w * as4.w;
                float pd = cv.x * ad4.x + cv.y * ad4.y + cv.z * ad4.z + cv.w * ad4.w;
#pragma unroll
                for (int o = 8; o; o >>= 1) {
                    ps += __shfl_xor_sync(0xFFFFFFFFu, ps, o);
                    pd += __shfl_xor_sync(0xFFFFFFFFu, pd, o);
                }
                if (tx == 0 && gr < n) { g_as[gr] = ps; g_ad[gr] = pd; }
            }
        }
    }
}

template <int K, int EPI>
__global__ __launch_bounds__(256) void k_gemm128(const float* __restrict__ A,
                                                 const float* __restrict__ B,
                                                 __half* __restrict__ C, int n,
                                                 const float* __restrict__ av1,
                                                 const float* __restrict__ av2) {
    gemm_body<K, EPI>(A, B, C, n, blockIdx.x, av1, av2);
}

// ---------------- fused: CSR fill blocks + layer-1 GEMM blocks ---------------
__global__ __launch_bounds__(256) void k_fill_gemm(const int* __restrict__ src,
                                                   const int* __restrict__ dst,
                                                   int e, int ebN,
                                                   const float* __restrict__ A,
                                                   const float* __restrict__ B,
                                                   __half* __restrict__ C, int n) {
    if ((int)blockIdx.x < ebN) {
        pdl_sync();                   // g_fill from k_scan_one
        int i = blockIdx.x * 256 + threadIdx.x;
        if (i < e) {
            int d = dst[i];
            int p = atomicAdd(&g_fill[d], 1);
            g_csrc[p] = src[i];
        }
        return;
    }
    gemm_body<32, 1>(A, B, C, n, blockIdx.x - ebN, nullptr, nullptr);
}

// ---------------- head GEMM + fused epilogue (fp32 A = h3, no tc buffer) ----
__global__ __launch_bounds__(256) void k_gemm_head(const float* __restrict__ A,
                                                   const float* __restrict__ B,
                                                   int n,
                                                   const float* __restrict__ bopt,
                                                   const float* __restrict__ bb1,
                                                   const float* __restrict__ Wb2,
                                                   const float* __restrict__ bb2,
                                                   float* __restrict__ optO,
                                                   float* __restrict__ botO,
                                                   float* __restrict__ geO,
                                                   float invn) {
    constexpr int K = 64, KT = 32;
    __shared__ __align__(16) float As[KT][132];
    __shared__ __align__(16) float Bs[K][64];
    __shared__ float sge[64];
    int t = threadIdx.x;
    int r0b = blockIdx.x * 128;
    int tx = t & 15, ty = t >> 4;

    if (t < 64) sge[t] = 0.f;
#pragma unroll
    for (int j = 0; j < (K * 64) / 256; j++) {
        int idx = t + j * 256;
        Bs[idx >> 6][idx & 63] = B[idx];   // g_wc written by kernel 1; chain-safe
    }

    pdl_sync();                       // A = h3 from predecessor

    ull acc[4][4] = {};

    for (int kt = 0; kt < K; kt += KT) {
        __syncthreads();
#pragma unroll
        for (int j = 0; j < (KT * 128) / 256; j++) {
            int idx = t + j * 256;
            int r = idx / KT, k = idx % KT;
            int gr = r0b + r;
            As[k][r] = (gr < n) ? A[gr * K + kt + k] : 0.f;
        }
        __syncthreads();
        {
            int kk = t & 31, r0 = (t >> 5) * 16;
            float gp = 0.f;
#pragma unroll
            for (int r = 0; r < 16; r++) gp += As[kk][r0 + r];
            atomicAdd(&sge[kt + kk], gp);
        }
#pragma unroll
        for (int kk = 0; kk < KT; kk++) {
            float4 bq = *(const float4*)&Bs[kt + kk][tx * 4];
            ull b0 = pack2(bq.x, bq.x), b1 = pack2(bq.y, bq.y);
            ull b2 = pack2(bq.z, bq.z), b3 = pack2(bq.w, bq.w);
            ulonglong2 aA = *(const ulonglong2*)&As[kk][ty * 8];
            ulonglong2 aB = *(const ulonglong2*)&As[kk][ty * 8 + 4];
            ffma2(acc[0][0], aA.x, b0); ffma2(acc[0][1], aA.x, b1);
            ffma2(acc[0][2], aA.x, b2); ffma2(acc[0][3], aA.x, b3);
            ffma2(acc[1][0], aA.y, b0); ffma2(acc[1][1], aA.y, b1);
            ffma2(acc[1][2], aA.y, b2); ffma2(acc[1][3], aA.y, b3);
            ffma2(acc[2][0], aB.x, b0); ffma2(acc[2][1], aB.x, b1);
            ffma2(acc[2][2], aB.x, b2); ffma2(acc[2][3], aB.x, b3);
            ffma2(acc[3][0], aB.y, b0); ffma2(acc[3][1], aB.y, b1);
            ffma2(acc[3][2], aB.y, b2); ffma2(acc[3][3], aB.y, b3);
        }
    }

    float bb2v = bb2[0];
    float boptv[4], bb1v[4], wb2v[4];
#pragma unroll
    for (int c4 = 0; c4 < 4; c4++) {
        int c = tx * 4 + c4;
        boptv[c4] = (c < 10) ? bopt[c] : 0.f;
        bb1v[c4]  = (c >= 10 && c < 42) ? bb1[c - 10] : 0.f;
        wb2v[c4]  = (c >= 10 && c < 42) ? Wb2[c - 10] : 0.f;
    }

#pragma unroll
    for (int rp = 0; rp < 4; rp++) {
        float2 c0 = unpack2(acc[rp][0]), c1 = unpack2(acc[rp][1]);
        float2 c2 = unpack2(acc[rp][2]), c3 = unpack2(acc[rp][3]);
        float vv[2][4] = { {c0.x, c1.x, c2.x, c3.x}, {c0.y, c1.y, c2.y, c3.y} };
#pragma unroll
        for (int h = 0; h < 2; h++) {
            int gr = r0b + ty * 8 + rp * 2 + h;
            float part = 0.f;
#pragma unroll
            for (int c4 = 0; c4 < 4; c4++)
                part += fmaxf(vv[h][c4] + bb1v[c4], 0.f) * wb2v[c4];
#pragma unroll
            for (int o = 8; o; o >>= 1)
                part += __shfl_xor_sync(0xFFFFFFFFu, part, o);
            if (gr < n) {
#pragma unroll
                for (int c4 = 0; c4 < 4; c4++) {
                    int c = tx * 4 + c4;
                    if (c < 10) optO[gr * 10 + c] = vv[h][c4] + boptv[c4];
                }
                if (tx == 0)
                    botO[gr] = 1.f / (1.f + __expf(-(part + bb2v)));
            }
        }
    }

    __syncthreads();
    if (t < 64) atomicAdd(&geO[t], sge[t] * invn);
}

// ---------------- GCN aggregation (fp16 gathers, full HADD2 tree) -----------
// lane owns col pair (2*lane, 2*lane+1); 4-edge groups summed in fp16.
__global__ void k_gcn_agg(const __half* __restrict__ t, const float* __restrict__ bias,
                          float* __restrict__ out, int n) {
    pdl_sync();                       // t / csrc from predecessor
    int w = (blockIdx.x * blockDim.x + threadIdx.x) >> 5;
    int lane = threadIdx.x & 31;
    if (w >= n) return;
    const uint* __restrict__ T = (const uint*)t;
    int s0 = g_rowptr[w], s1 = g_rowptr[w + 1];
    float2 acc = h2f(T[w * 32 + lane]);      // self-loop (pre-scaled)
    int e = s0;
    for (; e + 3 < s1; e += 4) {             // 4 independent loads in flight
        int i0 = g_csrc[e], i1 = g_csrc[e + 1], i2 = g_csrc[e + 2], i3 = g_csrc[e + 3];
        uint v0 = T[i0 * 32 + lane], v1 = T[i1 * 32 + lane];
        uint v2 = T[i2 * 32 + lane], v3 = T[i3 * 32 + lane];
        uint h03 = hadd2u(hadd2u(v0, v1), hadd2u(v2, v3));   // fp16 tree
        float2 f = h2f(h03);
        acc.x += f.x; acc.y += f.y;
    }
    if (e + 1 < s1) {
        int i0 = g_csrc[e], i1 = g_csrc[e + 1];
        uint h01 = hadd2u(T[i0 * 32 + lane], T[i1 * 32 + lane]);
        float2 f = h2f(h01);
        acc.x += f.x; acc.y += f.y;
        e += 2;
    }
    if (e < s1) {
        float2 f = h2f(T[g_csrc[e] * 32 + lane]);
        acc.x += f.x; acc.y += f.y;
    }
    float di = g_dinv[w];
    float2 bp = *(const float2*)&bias[lane * 2];
    float2 o = make_float2(fmaxf(acc.x * di + bp.x, 0.f), fmaxf(acc.y * di + bp.y, 0.f));
    *(float2*)&out[w * 64 + lane * 2] = o;
}

// ---------------- GAT aggregation (re-zeroes g_deg; fp16 feature gathers) ---
__global__ void k_gat(const __half* __restrict__ t, const float* __restrict__ bias,
                      float* __restrict__ out, int n) {
    pdl_sync();                       // t / g_as / g_ad from predecessor
    int gid = blockIdx.x * blockDim.x + threadIdx.x;
    if (gid < n) g_deg[gid] = 0;   // consumed by scan; reset for next replay
    int w = gid >> 5;
    int lane = threadIdx.x & 31;
    if (w >= n) return;
    const uint* __restrict__ T = (const uint*)t;
    int s0 = g_rowptr[w], s1 = g_rowptr[w + 1];
    int deg = s1 - s0;
    float adi = g_ad[w];
    float eself = leaky(g_as[w] + adi);
    float2 acc = make_float2(0.f, 0.f);

    if (deg <= 128) {
        int cs[4];
        float pv[4];
        float m = eself;
#pragma unroll
        for (int j = 0; j < 4; j++) {
            int e = s0 + j * 32 + lane;
            if (e < s1) {
                int s = g_csrc[e];
                cs[j] = s;
                float v = leaky(g_as[s] + adi);
                pv[j] = v;
                m = fmaxf(m, v);
            } else { cs[j] = 0; pv[j] = -1e30f; }
        }
#pragma unroll
        for (int o = 16; o; o >>= 1) m = fmaxf(m, __shfl_xor_sync(0xFFFFFFFFu, m, o));

        float sum = 0.f;
#pragma unroll
        for (int j = 0; j < 4; j++) {
            pv[j] = __expf(pv[j] - m);   // inactive lanes underflow to 0
            sum += pv[j];
        }
#pragma unroll
        for (int o = 16; o; o >>= 1) sum += __shfl_xor_sync(0xFFFFFFFFu, sum, o);
        float es = __expf(eself - m);
        float inv = 1.f / (sum + es);

        {
            float ps = es * inv;
            float2 sv = h2f(T[w * 32 + lane]);
            acc.x = sv.x * ps; acc.y = sv.y * ps;
        }

#pragma unroll
        for (int j = 0; j < 4; j++) {
            int base = s0 + j * 32;
            if (base >= s1) break;
            int cnt = min(32, s1 - base);
            int l = 0;
            for (; l + 1 < cnt; l += 2) {
                int   sA = __shfl_sync(0xFFFFFFFFu, cs[j], l);
                int   sB = __shfl_sync(0xFFFFFFFFu, cs[j], l + 1);
                float pA = __shfl_sync(0xFFFFFFFFu, pv[j], l) * inv;
                float pB = __shfl_sync(0xFFFFFFFFu, pv[j], l + 1) * inv;
                uint vA = T[sA * 32 + lane], vB = T[sB * 32 + lane];
                float2 fA = h2f(vA), fB = h2f(vB);
                acc.x = fmaf(fA.x, pA, acc.x); acc.y = fmaf(fA.y, pA, acc.y);
                acc.x = fmaf(fB.x, pB, acc.x); acc.y = fmaf(fB.y, pB, acc.y);
            }
            if (l < cnt) {
                int   sA = __shfl_sync(0xFFFFFFFFu, cs[j], l);
                float pA = __shfl_sync(0xFFFFFFFFu, pv[j], l) * inv;
                float2 fA = h2f(T[sA * 32 + lane]);
                acc.x = fmaf(fA.x, pA, acc.x); acc.y = fmaf(fA.y, pA, acc.y);
            }
        }
    } else {
        // fallback: 3-pass via g_p (deg > 128)
        float m = eself;
        for (int e = s0 + lane; e < s1; e += 32) {
            float v = leaky(g_as[g_csrc[e]] + adi);
            g_p[e] = v;
            m = fmaxf(m, v);
        }
#pragma unroll
        for (int o = 16; o; o >>= 1) m = fmaxf(m, __shfl_xor_sync(0xFFFFFFFFu, m, o));
        float sum = 0.f;
        for (int e = s0 + lane; e < s1; e += 32) {
            float pe = __expf(g_p[e] - m);
            g_p[e] = pe;
            sum += pe;
        }
#pragma unroll
        for (int o = 16; o; o >>= 1) sum += __shfl_xor_sync(0xFFFFFFFFu, sum, o);
        float es = __expf(eself - m);
        float inv = 1.f / (sum + es);
        float ps = es * inv;
        float2 sv = h2f(T[w * 32 + lane]);
        acc.x = sv.x * ps; acc.y = sv.y * ps;
        for (int e = s0; e < s1; e++) {
            int sA = g_csrc[e];
            float aA = g_p[e] * inv;
            float2 f = h2f(T[sA * 32 + lane]);
            acc.x = fmaf(f.x, aA, acc.x); acc.y = fmaf(f.y, aA, acc.y);
        }
    }
    float2 bp = *(const float2*)&bias[lane * 2];
    float2 o = make_float2(fmaxf(acc.x + bp.x, 0.f), fmaxf(acc.y + bp.y, 0.f));
    *(float2*)&out[w * 64 + lane * 2] = o;
}

// ---------------- PDL launch helper ----------------
static inline void pdl_launch(const void* fn, int grid, int block,
                              void** args, bool pdl) {
    cudaLaunchConfig_t cfg;
    memset(&cfg, 0, sizeof(cfg));
    cfg.gridDim = dim3((unsigned)grid, 1, 1);
    cfg.blockDim = dim3((unsigned)block, 1, 1);
    cfg.stream = 0;
    cudaLaunchAttribute at;
    if (pdl) {
        at.id = cudaLaunchAttributeProgrammaticStreamSerialization;
        at.val.programmaticStreamSerializationAllowed = 1;
        cfg.attrs = &at;
        cfg.numAttrs = 1;
    }
    cudaLaunchKernelExC(&cfg, fn, args);
}

// ---------------- launcher ----------------
extern "C" void kernel_launch(void* const* d_in, const int* in_sizes, int n_in,
                              void* d_out, int out_size) {
    const float* x     = (const float*)d_in[0];
    const int*   ei    = (const int*)d_in[1];
    const float* W1    = (const float*)d_in[2];
    const float* b1    = (const float*)d_in[3];
    const float* W2    = (const float*)d_in[4];
    const float* a_src = (const float*)d_in[5];
    const float* a_dst = (const float*)d_in[6];
    const float* b2    = (const float*)d_in[7];
    const float* W3    = (const float*)d_in[8];
    const float* b3    = (const float*)d_in[9];
    const float* Wopt  = (const float*)d_in[10];
    const float* bopt  = (const float*)d_in[11];
    const float* Wb1   = (const float*)d_in[12];
    const float* bb1   = (const float*)d_in[13];
    const float* Wb2   = (const float*)d_in[14];
    const float* bb2   = (const float*)d_in[15];

    int n = in_sizes[0] / 32;
    int e = in_sizes[1] / 2;
    const int* src = ei;
    const int* dst = ei + e;

    float* out  = (float*)d_out;
    float* optO = out;
    float* botO = out + (size_t)n * 10;
    float* geO  = botO + n;

    __half* p_t;
    float *p_h, *p_wc;
    cudaGetSymbolAddress((void**)&p_t, g_t);
    cudaGetSymbolAddress((void**)&p_h, g_h);
    cudaGetSymbolAddress((void**)&p_wc, g_wc);

    int eb256  = (e + 255) / 256;
    int warpsB = (n + 7) / 8;
    int gemmB  = (n + 127) / 128;
    int scanB  = (n + 1023) / 1024;
    float invn = 1.0f / (float)n;

    // 1) count + init (no PDL: first kernel)
    {
        int grid = eb256 + 17;
        void* args[] = {(void*)&dst, (void*)&e, (void*)&eb256, (void*)&geO,
                        (void*)&Wopt, (void*)&Wb1};
        pdl_launch((const void*)k_count_init, grid, 256, args, false);
    }
    // 2) scan
    {
        void* args[] = {(void*)&n, (void*)&e};
        pdl_launch((const void*)k_scan_one, scanB, 256, args, true);
    }
    // 3) CSR fill + layer-1 GEMM
    {
        int grid = eb256 + gemmB;
        void* args[] = {(void*)&src, (void*)&dst, (void*)&e, (void*)&eb256,
                        (void*)&x, (void*)&W1, (void*)&p_t, (void*)&n};
        pdl_launch((const void*)k_fill_gemm, grid, 256, args, true);
    }
    // 4) GCN aggregation 1
    {
        void* args[] = {(void*)&p_t, (void*)&b1, (void*)&p_h, (void*)&n};
        pdl_launch((const void*)k_gcn_agg, warpsB, 256, args, true);
    }
    // 5) GAT GEMM (emits alphas)
    {
        void* args[] = {(void*)&p_h, (void*)&W2, (void*)&p_t, (void*)&n,
                        (void*)&a_src, (void*)&a_dst};
        pdl_launch((const void*)k_gemm128<64, 2>, gemmB, 256, args, true);
    }
    // 6) GAT aggregation
    {
        void* args[] = {(void*)&p_t, (void*)&b2, (void*)&p_h, (void*)&n};
        pdl_launch((const void*)k_gat, warpsB, 256, args, true);
    }
    // 7) layer-3 GEMM
    {
        const float* nul = nullptr;
        void* args[] = {(void*)&p_h, (void*)&W3, (void*)&p_t, (void*)&n,
                        (void*)&nul, (void*)&nul};
        pdl_launch((const void*)k_gemm128<64, 1>, gemmB, 256, args, true);
    }
    // 8) GCN aggregation 2
    {
        void* args[] = {(void*)&p_t, (void*)&b3, (void*)&p_h, (void*)&n};
        pdl_launch((const void*)k_gcn_agg, warpsB, 256, args, true);
    }
    // 9) head GEMM + fused epilogue
    {
        void* args[] = {(void*)&p_h, (void*)&p_wc, (void*)&n,
                        (void*)&bopt, (void*)&bb1, (void*)&Wb2, (void*)&bb2,
                        (void*)&optO, (void*)&botO, (void*)&geO, (void*)&invn};
        pdl_launch((const void*)k_gemm_head, gemmB, 256, args, true);
    }
}

// round 17
// speedup vs baseline: 1.2450x; 1.0342x over previous
#include <cuda_runtime.h>
#include <cuda_fp16.h>
#include <math.h>

#define NMAX 100000
#define EMAX 1250000
#define HDIM 64
#define SCAN_READY (1 << 30)

typedef unsigned long long ull;
typedef unsigned int uint;

// ---------------- scratch (static device globals; no allocs) ----------------
__device__ __align__(16) __half g_t[NMAX * HDIM];   // fp16 gathered intermediate
__device__ __align__(16) float g_h[NMAX * HDIM];
__device__ __align__(16) int   g_deg[NMAX];
__device__ float g_dinv[NMAX];
__device__ int   g_rowptr[NMAX + 1];
__device__ int   g_fill[NMAX];
__device__ int   g_csrc[EMAX];
__device__ float g_as[NMAX];
__device__ float g_ad[NMAX];
__device__ float g_p[EMAX];          // fallback path only (deg > 128)
__device__ __align__(16) float g_wc[64 * 64];
__device__ int   g_bsum[128];

__device__ __forceinline__ float leaky(float v) { return v > 0.f ? v : 0.2f * v; }

__device__ __forceinline__ void pdl_sync() {
#if defined(__CUDA_ARCH__) && (__CUDA_ARCH__ >= 900)
    cudaGridDependencySynchronize();
#endif
}

__device__ __forceinline__ void ffma2(ull& acc, ull a, ull b) {
    asm("fma.rn.f32x2 %0, %1, %2, %0;" : "+l"(acc) : "l"(a), "l"(b));
}
__device__ __forceinline__ ull pack2(float lo, float hi) {
    ull r;
    asm("mov.b64 %0, {%1, %2};" : "=l"(r) : "f"(lo), "f"(hi));
    return r;
}
__device__ __forceinline__ float2 unpack2(ull v) {
    float2 r;
    asm("mov.b64 {%0, %1}, %2;" : "=f"(r.x), "=f"(r.y) : "l"(v));
    return r;
}
// half2 (as uint) -> float2
__device__ __forceinline__ float2 h2f(uint v) {
    __half2 h = *reinterpret_cast<__half2*>(&v);
    return __half22float2(h);
}
__device__ __forceinline__ uint f2h(float a, float b) {
    __half2 h = __float22half2_rn(make_float2(a, b));
    return *reinterpret_cast<uint*>(&h);
}
// fp16 pairwise add of two half2 words (HADD2)
__device__ __forceinline__ uint hadd2u(uint a, uint b) {
    __half2 r = __hadd2(*reinterpret_cast<__half2*>(&a),
                        *reinterpret_cast<__half2*>(&b));
    return *reinterpret_cast<uint*>(&r);
}

// ---------------- count + init (geO zero, bsum flags zero, packed Wc) -------
__global__ void k_count_init(const int* __restrict__ dst, int e, int ebN,
                             float* __restrict__ geO,
                             const float* __restrict__ Wopt,
                             const float* __restrict__ Wb1) {
    int b = blockIdx.x;
    if (b < ebN) {
        int i = b * 256 + threadIdx.x;
        if (i < e) atomicAdd(&g_deg[dst[i]], 1);
        return;
    }
    int i = (b - ebN) * 256 + threadIdx.x;
    if (i < 64) geO[i] = 0.f;
    if (i < 128) g_bsum[i] = 0;
    if (i < 4096) {
        int k = i >> 6, c = i & 63;
        float v = 0.f;
        if (c < 10) v = Wopt[k * 10 + c];
        else if (c < 42) v = Wb1[k * 32 + (c - 10)];
        g_wc[i] = v;
    }
}

// ------------- single-pass exclusive scan with parallel lookback ------------
__global__ void k_scan_one(int n, int e) {
    __shared__ int sm[256];
    __shared__ int sl[256];
    pdl_sync();                       // g_deg from k_count_init
    int b = blockIdx.x, t = threadIdx.x;
    int base = b * 1024 + t * 4;
    int d[4];
    int s = 0;
#pragma unroll
    for (int j = 0; j < 4; j++) {
        int i = base + j;
        d[j] = (i < n) ? g_deg[i] : 0;
        s += d[j];
    }
    sm[t] = s;
    __syncthreads();
#pragma unroll
    for (int off = 1; off < 256; off <<= 1) {
        int v = (t >= off) ? sm[t - off] : 0;
        __syncthreads();
        sm[t] += v;
        __syncthreads();
    }
    if (t == 0) atomicExch(&g_bsum[b], sm[255] | SCAN_READY);

    int part = 0;
    if (t < b) {
        volatile int* vb = g_bsum;
        int v;
        do { v = vb[t]; } while (!(v & SCAN_READY));
        part = v & (SCAN_READY - 1);
    }
    sl[t] = part;
    __syncthreads();
#pragma unroll
    for (int off = 128; off; off >>= 1) {
        if (t < off) sl[t] += sl[t + off];
        __syncthreads();
    }
    int run = sl[0] + sm[t] - s;
#pragma unroll
    for (int j = 0; j < 4; j++) {
        int i = base + j;
        if (i < n) {
            g_rowptr[i] = run;
            g_fill[i] = run;
            g_dinv[i] = rsqrtf((float)(d[j] + 1));  // +1 self-loop
            run += d[j];
        }
    }
    if (b == 0 && t == 0) g_rowptr[n] = e;
}

// ---------------- GEMM body: C[n,64](fp16) = A[n,K](fp32) @ B[K,64] ---------
// EPI: 0 plain | 1 scale row by g_dinv[row] | 2 also emit g_as/g_ad
// Weight (B) smem loads happen BEFORE pdl_sync (independent of predecessor).
template <int K, int EPI>
__device__ __forceinline__ void gemm_body(const float* __restrict__ A,
                                          const float* __restrict__ B,
                                          __half* __restrict__ C, int n, int bid,
                                          const float* __restrict__ av1,
                                          const float* __restrict__ av2) {
    constexpr int KT = (K > 32) ? 32 : K;
    __shared__ __align__(16) float As[KT][132];
    __shared__ __align__(16) float Bs[K][64];
    int t = threadIdx.x;
    int r0b = bid * 128;
    int tx = t & 15, ty = t >> 4;

#pragma unroll
    for (int j = 0; j < (K * 64) / 256; j++) {
        int idx = t + j * 256;
        Bs[idx >> 6][idx & 63] = B[idx];
    }

    pdl_sync();                       // A (and g_dinv) may come from predecessor

    ull acc[4][4] = {};

    for (int kt = 0; kt < K; kt += KT) {
        __syncthreads();
#pragma unroll
        for (int j = 0; j < (KT * 128) / 256; j++) {
            int idx = t + j * 256;
            int r = idx / KT, k = idx % KT;
            int gr = r0b + r;
            As[k][r] = (gr < n) ? A[gr * K + kt + k] : 0.f;
        }
        __syncthreads();
#pragma unroll
        for (int kk = 0; kk < KT; kk++) {
            float4 bq = *(const float4*)&Bs[kt + kk][tx * 4];
            ull b0 = pack2(bq.x, bq.x), b1 = pack2(bq.y, bq.y);
            ull b2 = pack2(bq.z, bq.z), b3 = pack2(bq.w, bq.w);
            ulonglong2 aA = *(const ulonglong2*)&As[kk][ty * 8];
            ulonglong2 aB = *(const ulonglong2*)&As[kk][ty * 8 + 4];
            ffma2(acc[0][0], aA.x, b0); ffma2(acc[0][1], aA.x, b1);
            ffma2(acc[0][2], aA.x, b2); ffma2(acc[0][3], aA.x, b3);
            ffma2(acc[1][0], aA.y, b0); ffma2(acc[1][1], aA.y, b1);
            ffma2(acc[1][2], aA.y, b2); ffma2(acc[1][3], aA.y, b3);
            ffma2(acc[2][0], aB.x, b0); ffma2(acc[2][1], aB.x, b1);
            ffma2(acc[2][2], aB.x, b2); ffma2(acc[2][3], aB.x, b3);
            ffma2(acc[3][0], aB.y, b0); ffma2(acc[3][1], aB.y, b1);
            ffma2(acc[3][2], aB.y, b2); ffma2(acc[3][3], aB.y, b3);
        }
    }

    float4 as4, ad4;
    if (EPI == 2) {
        as4 = *(const float4*)&av1[tx * 4];
        ad4 = *(const float4*)&av2[tx * 4];
    }
#pragma unroll
    for (int rp = 0; rp < 4; rp++) {
        float2 c0 = unpack2(acc[rp][0]), c1 = unpack2(acc[rp][1]);
        float2 c2 = unpack2(acc[rp][2]), c3 = unpack2(acc[rp][3]);
        float4 v[2] = { make_float4(c0.x, c1.x, c2.x, c3.x),
                        make_float4(c0.y, c1.y, c2.y, c3.y) };
#pragma unroll
        for (int h = 0; h < 2; h++) {
            int gr = r0b + ty * 8 + rp * 2 + h;
            float4 cv = v[h];
            if (EPI == 1 && gr < n) {
                float s = g_dinv[gr];
                cv.x *= s; cv.y *= s; cv.z *= s; cv.w *= s;
            }
            if (gr < n) {
                uint2 st = make_uint2(f2h(cv.x, cv.y), f2h(cv.z, cv.w));
                *(uint2*)&C[gr * 64 + tx * 4] = st;   // STG.64, fp16 row
            }
            if (EPI == 2) {
                float ps = cv.x * as4.x + cv.y * as4.y + cv.z * as4.z + cv.w * as4.w;
                float pd = cv.x * ad4.x + cv.y * ad4.y + cv.z * ad4.z + cv.w * ad4.w;
#pragma unroll
                for (int o = 8; o; o >>= 1) {
                    ps += __shfl_xor_sync(0xFFFFFFFFu, ps, o);
                    pd += __shfl_xor_sync(0xFFFFFFFFu, pd, o);
                }
                if (tx == 0 && gr < n) { g_as[gr] = ps; g_ad[gr] = pd; }
            }
        }
    }
}

template <int K, int EPI>
__global__ __launch_bounds__(256) void k_gemm128(const float* __restrict__ A,
                                                 const float* __restrict__ B,
                                                 __half* __restrict__ C, int n,
                                                 const float* __restrict__ av1,
                                                 const float* __restrict__ av2) {
    gemm_body<K, EPI>(A, B, C, n, blockIdx.x, av1, av2);
}

// ---------------- fused: CSR fill blocks + layer-1 GEMM blocks ---------------
__global__ __launch_bounds__(256) void k_fill_gemm(const int* __restrict__ src,
                                                   const int* __restrict__ dst,
                                                   int e, int ebN,
                                                   const float* __restrict__ A,
                                                   const float* __restrict__ B,
                                                   __half* __restrict__ C, int n) {
    if ((int)blockIdx.x < ebN) {
        pdl_sync();                   // g_fill from k_scan_one
        int i = blockIdx.x * 256 + threadIdx.x;
        if (i < e) {
            int d = dst[i];
            int p = atomicAdd(&g_fill[d], 1);
            g_csrc[p] = src[i];
        }
        return;
    }
    gemm_body<32, 1>(A, B, C, n, blockIdx.x - ebN, nullptr, nullptr);
}

// ---------------- head GEMM + fused epilogue (fp32 A = h3, no tc buffer) ----
__global__ __launch_bounds__(256) void k_gemm_head(const float* __restrict__ A,
                                                   const float* __restrict__ B,
                                                   int n,
                                                   const float* __restrict__ bopt,
                                                   const float* __restrict__ bb1,
                                                   const float* __restrict__ Wb2,
                                                   const float* __restrict__ bb2,
                                                   float* __restrict__ optO,
                                                   float* __restrict__ botO,
                                                   float* __restrict__ geO,
                                                   float invn) {
    constexpr int K = 64, KT = 32;
    __shared__ __align__(16) float As[KT][132];
    __shared__ __align__(16) float Bs[K][64];
    __shared__ float sge[64];
    int t = threadIdx.x;
    int r0b = blockIdx.x * 128;
    int tx = t & 15, ty = t >> 4;

    if (t < 64) sge[t] = 0.f;
#pragma unroll
    for (int j = 0; j < (K * 64) / 256; j++) {
        int idx = t + j * 256;
        Bs[idx >> 6][idx & 63] = B[idx];   // g_wc written by kernel 1; chain-safe
    }

    pdl_sync();                       // A = h3 from predecessor

    ull acc[4][4] = {};

    for (int kt = 0; kt < K; kt += KT) {
        __syncthreads();
#pragma unroll
        for (int j = 0; j < (KT * 128) / 256; j++) {
            int idx = t + j * 256;
            int r = idx / KT, k = idx % KT;
            int gr = r0b + r;
            As[k][r] = (gr < n) ? A[gr * K + kt + k] : 0.f;
        }
        __syncthreads();
        {
            int kk = t & 31, r0 = (t >> 5) * 16;
            float gp = 0.f;
#pragma unroll
            for (int r = 0; r < 16; r++) gp += As[kk][r0 + r];
            atomicAdd(&sge[kt + kk], gp);
        }
#pragma unroll
        for (int kk = 0; kk < KT; kk++) {
            float4 bq = *(const float4*)&Bs[kt + kk][tx * 4];
            ull b0 = pack2(bq.x, bq.x), b1 = pack2(bq.y, bq.y);
            ull b2 = pack2(bq.z, bq.z), b3 = pack2(bq.w, bq.w);
            ulonglong2 aA = *(const ulonglong2*)&As[kk][ty * 8];
            ulonglong2 aB = *(const ulonglong2*)&As[kk][ty * 8 + 4];
            ffma2(acc[0][0], aA.x, b0); ffma2(acc[0][1], aA.x, b1);
            ffma2(acc[0][2], aA.x, b2); ffma2(acc[0][3], aA.x, b3);
            ffma2(acc[1][0], aA.y, b0); ffma2(acc[1][1], aA.y, b1);
            ffma2(acc[1][2], aA.y, b2); ffma2(acc[1][3], aA.y, b3);
            ffma2(acc[2][0], aB.x, b0); ffma2(acc[2][1], aB.x, b1);
            ffma2(acc[2][2], aB.x, b2); ffma2(acc[2][3], aB.x, b3);
            ffma2(acc[3][0], aB.y, b0); ffma2(acc[3][1], aB.y, b1);
            ffma2(acc[3][2], aB.y, b2); ffma2(acc[3][3], aB.y, b3);
        }
    }

    float bb2v = bb2[0];
    float boptv[4], bb1v[4], wb2v[4];
#pragma unroll
    for (int c4 = 0; c4 < 4; c4++) {
        int c = tx * 4 + c4;
        boptv[c4] = (c < 10) ? bopt[c] : 0.f;
        bb1v[c4]  = (c >= 10 && c < 42) ? bb1[c - 10] : 0.f;
        wb2v[c4]  = (c >= 10 && c < 42) ? Wb2[c - 10] : 0.f;
    }

#pragma unroll
    for (int rp = 0; rp < 4; rp++) {
        float2 c0 = unpack2(acc[rp][0]), c1 = unpack2(acc[rp][1]);
        float2 c2 = unpack2(acc[rp][2]), c3 = unpack2(acc[rp][3]);
        float vv[2][4] = { {c0.x, c1.x, c2.x, c3.x}, {c0.y, c1.y, c2.y, c3.y} };
#pragma unroll
        for (int h = 0; h < 2; h++) {
            int gr = r0b + ty * 8 + rp * 2 + h;
            float part = 0.f;
#pragma unroll
            for (int c4 = 0; c4 < 4; c4++)
                part += fmaxf(vv[h][c4] + bb1v[c4], 0.f) * wb2v[c4];
#pragma unroll
            for (int o = 8; o; o >>= 1)
                part += __shfl_xor_sync(0xFFFFFFFFu, part, o);
            if (gr < n) {
#pragma unroll
                for (int c4 = 0; c4 < 4; c4++) {
                    int c = tx * 4 + c4;
                    if (c < 10) optO[gr * 10 + c] = vv[h][c4] + boptv[c4];
                }
                if (tx == 0)
                    botO[gr] = 1.f / (1.f + __expf(-(part + bb2v)));
            }
        }
    }

    __syncthreads();
    if (t < 64) atomicAdd(&geO[t], sge[t] * invn);
}

// ---------------- GCN aggregation: HALF-WARP per node, fp16 uint2 gathers ---
// Each 16-lane half independently owns a node (2 independent latency chains
// per warp). Lane li owns cols li*4..li*4+3 (uint2 = 2x half2 = 8 B;
// 16 lanes x 8 B = full 128 B row). No cross-half reduction.
__global__ void k_gcn_agg(const __half* __restrict__ t, const float* __restrict__ bias,
                          float* __restrict__ out, int n) {
    pdl_sync();                       // t / csrc from predecessor
    int gid = blockIdx.x * blockDim.x + threadIdx.x;
    int lane = threadIdx.x & 31;
    int half = lane >> 4, li = lane & 15;
    int nd = (gid >> 5) * 2 + half;   // 2 nodes per warp
    if (nd >= n) return;
    const uint2* __restrict__ T2 = (const uint2*)t;
    int s0 = g_rowptr[nd], s1 = g_rowptr[nd + 1];
    uint2 sv = T2[nd * 16 + li];      // self-loop (pre-scaled)
    float2 aLo = h2f(sv.x), aHi = h2f(sv.y);
    int e = s0;
    for (; e + 3 < s1; e += 4) {      // 4 uint2 loads in flight per half
        int i0 = g_csrc[e], i1 = g_csrc[e + 1], i2 = g_csrc[e + 2], i3 = g_csrc[e + 3];
        uint2 v0 = T2[i0 * 16 + li], v1 = T2[i1 * 16 + li];
        uint2 v2 = T2[i2 * 16 + li], v3 = T2[i3 * 16 + li];
        uint hLo = hadd2u(hadd2u(v0.x, v1.x), hadd2u(v2.x, v3.x));
        uint hHi = hadd2u(hadd2u(v0.y, v1.y), hadd2u(v2.y, v3.y));
        float2 fLo = h2f(hLo), fHi = h2f(hHi);
        aLo.x += fLo.x; aLo.y += fLo.y;
        aHi.x += fHi.x; aHi.y += fHi.y;
    }
    if (e + 1 < s1) {
        int i0 = g_csrc[e], i1 = g_csrc[e + 1];
        uint2 v0 = T2[i0 * 16 + li], v1 = T2[i1 * 16 + li];
        uint hLo = hadd2u(v0.x, v1.x), hHi = hadd2u(v0.y, v1.y);
        float2 fLo = h2f(hLo), fHi = h2f(hHi);
        aLo.x += fLo.x; aLo.y += fLo.y;
        aHi.x += fHi.x; aHi.y += fHi.y;
        e += 2;
    }
    if (e < s1) {
        uint2 v = T2[g_csrc[e] * 16 + li];
        float2 fLo = h2f(v.x), fHi = h2f(v.y);
        aLo.x += fLo.x; aLo.y += fLo.y;
        aHi.x += fHi.x; aHi.y += fHi.y;
    }
    float di = g_dinv[nd];
    float4 bp = *(const float4*)&bias[li * 4];
    float4 o = make_float4(fmaxf(aLo.x * di + bp.x, 0.f),
                           fmaxf(aLo.y * di + bp.y, 0.f),
                           fmaxf(aHi.x * di + bp.z, 0.f),
                           fmaxf(aHi.y * di + bp.w, 0.f));
    *(float4*)&out[nd * 64 + li * 4] = o;
}

// ---------------- GAT aggregation (re-zeroes g_deg; fp16 feature gathers) ---
__global__ void k_gat(const __half* __restrict__ t, const float* __restrict__ bias,
                      float* __restrict__ out, int n) {
    pdl_sync();                       // t / g_as / g_ad from predecessor
    int gid = blockIdx.x * blockDim.x + threadIdx.x;
    if (gid < n) g_deg[gid] = 0;   // consumed by scan; reset for next replay
    int w = gid >> 5;
    int lane = threadIdx.x & 31;
    if (w >= n) return;
    const uint* __restrict__ T = (const uint*)t;
    int s0 = g_rowptr[w], s1 = g_rowptr[w + 1];
    int deg = s1 - s0;
    float adi = g_ad[w];
    float eself = leaky(g_as[w] + adi);
    float2 acc = make_float2(0.f, 0.f);

    if (deg <= 128) {
        int cs[4];
        float pv[4];
        float m = eself;
#pragma unroll
        for (int j = 0; j < 4; j++) {
            int e = s0 + j * 32 + lane;
            if (e < s1) {
                int s = g_csrc[e];
                cs[j] = s;
                float v = leaky(g_as[s] + adi);
                pv[j] = v;
                m = fmaxf(m, v);
            } else { cs[j] = 0; pv[j] = -1e30f; }
        }
#pragma unroll
        for (int o = 16; o; o >>= 1) m = fmaxf(m, __shfl_xor_sync(0xFFFFFFFFu, m, o));

        float sum = 0.f;
#pragma unroll
        for (int j = 0; j < 4; j++) {
            pv[j] = __expf(pv[j] - m);   // inactive lanes underflow to 0
            sum += pv[j];
        }
#pragma unroll
        for (int o = 16; o; o >>= 1) sum += __shfl_xor_sync(0xFFFFFFFFu, sum, o);
        float es = __expf(eself - m);
        float inv = 1.f / (sum + es);

        {
            float ps = es * inv;
            float2 sv = h2f(T[w * 32 + lane]);
            acc.x = sv.x * ps; acc.y = sv.y * ps;
        }

#pragma unroll
        for (int j = 0; j < 4; j++) {
            int base = s0 + j * 32;
            if (base >= s1) break;
            int cnt = min(32, s1 - base);
            int l = 0;
            for (; l + 1 < cnt; l += 2) {
                int   sA = __shfl_sync(0xFFFFFFFFu, cs[j], l);
                int   sB = __shfl_sync(0xFFFFFFFFu, cs[j], l + 1);
                float pA = __shfl_sync(0xFFFFFFFFu, pv[j], l) * inv;
                float pB = __shfl_sync(0xFFFFFFFFu, pv[j], l + 1) * inv;
                uint vA = T[sA * 32 + lane], vB = T[sB * 32 + lane];
                float2 fA = h2f(vA), fB = h2f(vB);
                acc.x = fmaf(fA.x, pA, acc.x); acc.y = fmaf(fA.y, pA, acc.y);
                acc.x = fmaf(fB.x, pB, acc.x); acc.y = fmaf(fB.y, pB, acc.y);
            }
            if (l < cnt) {
                int   sA = __shfl_sync(0xFFFFFFFFu, cs[j], l);
                float pA = __shfl_sync(0xFFFFFFFFu, pv[j], l) * inv;
                float2 fA = h2f(T[sA * 32 + lane]);
                acc.x = fmaf(fA.x, pA, acc.x); acc.y = fmaf(fA.y, pA, acc.y);
            }
        }
    } else {
        // fallback: 3-pass via g_p (deg > 128)
        float m = eself;
        for (int e = s0 + lane; e < s1; e += 32) {
            float v = leaky(g_as[g_csrc[e]] + adi);
            g_p[e] = v;
            m = fmaxf(m, v);
        }
#pragma unroll
        for (int o = 16; o; o >>= 1) m = fmaxf(m, __shfl_xor_sync(0xFFFFFFFFu, m, o));
        float sum = 0.f;
        for (int e = s0 + lane; e < s1; e += 32) {
            float pe = __expf(g_p[e] - m);
            g_p[e] = pe;
            sum += pe;
        }
#pragma unroll
        for (int o = 16; o; o >>= 1) sum += __shfl_xor_sync(0xFFFFFFFFu, sum, o);
        float es = __expf(eself - m);
        float inv = 1.f / (sum + es);
        float ps = es * inv;
        float2 sv = h2f(T[w * 32 + lane]);
        acc.x = sv.x * ps; acc.y = sv.y * ps;
        for (int e = s0; e < s1; e++) {
            int sA = g_csrc[e];
            float aA = g_p[e] * inv;
            float2 f = h2f(T[sA * 32 + lane]);
            acc.x = fmaf(f.x, aA, acc.x); acc.y = fmaf(f.y, aA, acc.y);
        }
    }
    float2 bp = *(const float2*)&bias[lane * 2];
    float2 o = make_float2(fmaxf(acc.x + bp.x, 0.f), fmaxf(acc.y + bp.y, 0.f));
    *(float2*)&out[w * 64 + lane * 2] = o;
}

// ---------------- PDL launch helper ----------------
static inline void pdl_launch(const void* fn, int grid, int block,
                              void** args, bool pdl) {
    cudaLaunchConfig_t cfg;
    memset(&cfg, 0, sizeof(cfg));
    cfg.gridDim = dim3((unsigned)grid, 1, 1);
    cfg.blockDim = dim3((unsigned)block, 1, 1);
    cfg.stream = 0;
    cudaLaunchAttribute at;
    if (pdl) {
        at.id = cudaLaunchAttributeProgrammaticStreamSerialization;
        at.val.programmaticStreamSerializationAllowed = 1;
        cfg.attrs = &at;
        cfg.numAttrs = 1;
    }
    cudaLaunchKernelExC(&cfg, fn, args);
}

// ---------------- launcher ----------------
extern "C" void kernel_launch(void* const* d_in, const int* in_sizes, int n_in,
                              void* d_out, int out_size) {
    const float* x     = (const float*)d_in[0];
    const int*   ei    = (const int*)d_in[1];
    const float* W1    = (const float*)d_in[2];
    const float* b1    = (const float*)d_in[3];
    const float* W2    = (const float*)d_in[4];
    const float* a_src = (const float*)d_in[5];
    const float* a_dst = (const float*)d_in[6];
    const float* b2    = (const float*)d_in[7];
    const float* W3    = (const float*)d_in[8];
    const float* b3    = (const float*)d_in[9];
    const float* Wopt  = (const float*)d_in[10];
    const float* bopt  = (const float*)d_in[11];
    const float* Wb1   = (const float*)d_in[12];
    const float* bb1   = (const float*)d_in[13];
    const float* Wb2   = (const float*)d_in[14];
    const float* bb2   = (const float*)d_in[15];

    int n = in_sizes[0] / 32;
    int e = in_sizes[1] / 2;
    const int* src = ei;
    const int* dst = ei + e;

    float* out  = (float*)d_out;
    float* optO = out;
    float* botO = out + (size_t)n * 10;
    float* geO  = botO + n;

    __half* p_t;
    float *p_h, *p_wc;
    cudaGetSymbolAddress((void**)&p_t, g_t);
    cudaGetSymbolAddress((void**)&p_h, g_h);
    cudaGetSymbolAddress((void**)&p_wc, g_wc);

    int eb256  = (e + 255) / 256;
    int warpsB = (n + 7) / 8;        // GAT: warp per node
    int gcnB   = (n + 15) / 16;      // GCN: half-warp per node (16 nodes/block)
    int gemmB  = (n + 127) / 128;
    int scanB  = (n + 1023) / 1024;
    float invn = 1.0f / (float)n;

    // 1) count + init (no PDL: first kernel)
    {
        int grid = eb256 + 17;
        void* args[] = {(void*)&dst, (void*)&e, (void*)&eb256, (void*)&geO,
                        (void*)&Wopt, (void*)&Wb1};
        pdl_launch((const void*)k_count_init, grid, 256, args, false);
    }
    // 2) scan
    {
        void* args[] = {(void*)&n, (void*)&e};
        pdl_launch((const void*)k_scan_one, scanB, 256, args, true);
    }
    // 3) CSR fill + layer-1 GEMM
    {
        int grid = eb256 + gemmB;
        void* args[] = {(void*)&src, (void*)&dst, (void*)&e, (void*)&eb256,
                        (void*)&x, (void*)&W1, (void*)&p_t, (void*)&n};
        pdl_launch((const void*)k_fill_gemm, grid, 256, args, true);
    }
    // 4) GCN aggregation 1
    {
        void* args[] = {(void*)&p_t, (void*)&b1, (void*)&p_h, (void*)&n};
        pdl_launch((const void*)k_gcn_agg, gcnB, 256, args, true);
    }
    // 5) GAT GEMM (emits alphas)
    {
        void* args[] = {(void*)&p_h, (void*)&W2, (void*)&p_t, (void*)&n,
                        (void*)&a_src, (void*)&a_dst};
        pdl_launch((const void*)k_gemm128<64, 2>, gemmB, 256, args, true);
    }
    // 6) GAT aggregation
    {
        void* args[] = {(void*)&p_t, (void*)&b2, (void*)&p_h, (void*)&n};
        pdl_launch((const void*)k_gat, warpsB, 256, args, true);
    }
    // 7) layer-3 GEMM
    {
        const float* nul = nullptr;
        void* args[] = {(void*)&p_h, (void*)&W3, (void*)&p_t, (void*)&n,
                        (void*)&nul, (void*)&nul};
        pdl_launch((const void*)k_gemm128<64, 1>, gemmB, 256, args, true);
    }
    // 8) GCN aggregation 2
    {
        void* args[] = {(void*)&p_t, (void*)&b3, (void*)&p_h, (void*)&n};
        pdl_launch((const void*)k_gcn_agg, gcnB, 256, args, true);
    }
    // 9) head GEMM + fused epilogue
    {
        void* args[] = {(void*)&p_h, (void*)&p_wc, (void*)&n,
                        (void*)&bopt, (void*)&bb1, (void*)&Wb2, (void*)&bb2,
                        (void*)&optO, (void*)&botO, (void*)&geO, (void*)&invn};
        pdl_launch((const void*)k_gemm_head, gemmB, 256, args, true);
    }
}